// round 10
// baseline (speedup 1.0000x reference)
#include <cuda_runtime.h>
#include <cuda_bf16.h>
#include <cstdint>
#include <math.h>

#define Bq 8192
#define Dd 1024
#define Kp 512
#define SEG 8
#define STAGES 5

// ============================ device globals (no allocs allowed) ============
__device__ __align__(16) __nv_bfloat16 g_cls_h[(size_t)Bq * Dd];
__device__ __align__(16) __nv_bfloat16 g_cls_l[(size_t)Bq * Dd];
__device__ __align__(16) __nv_bfloat16 g_p_h[(size_t)Kp * Dd];
__device__ __align__(16) __nv_bfloat16 g_p_l[(size_t)Kp * Dd];
__device__ __align__(16) __nv_bfloat16 g_r_h[(size_t)Bq * Kp];
__device__ __align__(16) __nv_bfloat16 g_r_l[(size_t)Bq * Kp];
__device__ __align__(16) float g_logits[(size_t)Bq * Kp];
__device__ __align__(16) float g_parts[(size_t)SEG * Kp * Dd];
__device__ int g_cnt[Bq / 128];   // zero-initialized; finishers reset -> invariant

// ============================ PTX helpers (base sm_103-safe) =================
__device__ __forceinline__ uint32_t smem_u32(const void* p) {
    uint32_t a;
    asm("{ .reg .u64 t; cvta.to.shared.u64 t, %1; cvt.u32.u64 %0, t; }" : "=r"(a) : "l"(p));
    return a;
}
#define CP_ASYNC16(sa, gp) \
    asm volatile("cp.async.cg.shared.global [%0], [%1], 16;" :: "r"(sa), "l"(gp))
#define CP_COMMIT() asm volatile("cp.async.commit_group;")
#define CP_WAIT1()  asm volatile("cp.async.wait_group 1;")
#define LDSM_X4(r0, r1, r2, r3, addr) \
    asm volatile("ldmatrix.sync.aligned.m8n8.x4.shared.b16 {%0,%1,%2,%3}, [%4];" \
        : "=r"(r0), "=r"(r1), "=r"(r2), "=r"(r3) : "r"(addr))
#define LDSM_X4T(r0, r1, r2, r3, addr) \
    asm volatile("ldmatrix.sync.aligned.m8n8.x4.trans.shared.b16 {%0,%1,%2,%3}, [%4];" \
        : "=r"(r0), "=r"(r1), "=r"(r2), "=r"(r3) : "r"(addr))
#define MMA16816(d, a, b0v, b1v) \
    asm volatile("mma.sync.aligned.m16n8k16.row.col.f32.bf16.bf16.f32 " \
        "{%0,%1,%2,%3}, {%4,%5,%6,%7}, {%8,%9}, {%0,%1,%2,%3};" \
        : "+f"((d)[0]), "+f"((d)[1]), "+f"((d)[2]), "+f"((d)[3]) \
        : "r"((a)[0]), "r"((a)[1]), "r"((a)[2]), "r"((a)[3]), "r"(b0v), "r"(b1v))

// Tiles: CTA 128x128, 8 warps (2x4), warp 64x32, 4x4 of m16n8, KC=32, 3 stages.
#define KC 32
#define SROW 40
#define TROW 136
#define NT_STG (128 * SROW * 2)        // 10240 B
#define TT_STG (KC * TROW * 2)         // 8704 B
#define SMEM_NT (6 * NT_STG)           // 61440
#define SMEM_TT (6 * TT_STG)           // 52224
#define SMEM_NN (3 * NT_STG + 3 * TT_STG)  // 56832

// ---------------- shared epilogue ----------------
__device__ __forceinline__ void epilogue(float acc[4][4][4], float* C, int ldc,
                                         int bm, int bn, int wm, int wn, int lane,
                                         const float* addsrc)
{
#pragma unroll
    for (int mt = 0; mt < 4; ++mt) {
        const int r0 = bm + wm * 64 + mt * 16 + (lane >> 2);
#pragma unroll
        for (int nt = 0; nt < 4; ++nt) {
            const int col = bn + wn * 32 + nt * 8 + (lane & 3) * 2;
            float2 v0 = make_float2(acc[mt][nt][0], acc[mt][nt][1]);
            float2 v1 = make_float2(acc[mt][nt][2], acc[mt][nt][3]);
            if (addsrc) {
                const float2 a0 = *(const float2*)(addsrc + (size_t)r0 * ldc + col);
                const float2 a1 = *(const float2*)(addsrc + (size_t)(r0 + 8) * ldc + col);
                v0.x += a0.x; v0.y += a0.y;
                v1.x += a1.x; v1.y += a1.y;
            }
            *(float2*)(C + (size_t)r0 * ldc + col) = v0;
            *(float2*)(C + (size_t)(r0 + 8) * ldc + col) = v1;
        }
    }
}

// ---------------- warp softmax over one 512-col row (lane owns 16 cols) -----
__device__ __forceinline__ void softmax_row(const float* __restrict__ Lrow,
                                            __nv_bfloat16* __restrict__ rh,
                                            __nv_bfloat16* __restrict__ rl,
                                            float* __restrict__ rfrow, int lane)
{
    const float4* Lr = (const float4*)Lrow;
    float4 v[4];
#pragma unroll
    for (int j = 0; j < 4; ++j) v[j] = Lr[lane + j * 32];

    float m = -1e30f;
#pragma unroll
    for (int j = 0; j < 4; ++j)
        m = fmaxf(m, fmaxf(fmaxf(v[j].x, v[j].y), fmaxf(v[j].z, v[j].w)));
#pragma unroll
    for (int o = 16; o; o >>= 1) m = fmaxf(m, __shfl_xor_sync(0xffffffffu, m, o));

    float4 e[4];
    float s = 0.f;
#pragma unroll
    for (int j = 0; j < 4; ++j) {
        e[j].x = __expf(v[j].x - m); e[j].y = __expf(v[j].y - m);
        e[j].z = __expf(v[j].z - m); e[j].w = __expf(v[j].w - m);
        s += (e[j].x + e[j].y) + (e[j].z + e[j].w);
    }
#pragma unroll
    for (int o = 16; o; o >>= 1) s += __shfl_xor_sync(0xffffffffu, s, o);

    const float inv = 1.0f / s;
    __nv_bfloat162* hp = (__nv_bfloat162*)rh;
    __nv_bfloat162* lp = (__nv_bfloat162*)rl;
    float4* rp = (float4*)rfrow;
#pragma unroll
    for (int j = 0; j < 4; ++j) {
        e[j].x *= inv; e[j].y *= inv; e[j].z *= inv; e[j].w *= inv;
        __nv_bfloat16 h0 = __float2bfloat16(e[j].x), h1 = __float2bfloat16(e[j].y);
        __nv_bfloat16 h2 = __float2bfloat16(e[j].z), h3 = __float2bfloat16(e[j].w);
        __nv_bfloat16 l0 = __float2bfloat16(e[j].x - __bfloat162float(h0));
        __nv_bfloat16 l1 = __float2bfloat16(e[j].y - __bfloat162float(h1));
        __nv_bfloat16 l2 = __float2bfloat16(e[j].z - __bfloat162float(h2));
        __nv_bfloat16 l3 = __float2bfloat16(e[j].w - __bfloat162float(h3));
        const int c2 = (lane + j * 32) * 2;
        hp[c2 + 0] = __halves2bfloat162(h0, h1);
        hp[c2 + 1] = __halves2bfloat162(h2, h3);
        lp[c2 + 0] = __halves2bfloat162(l0, l1);
        lp[c2 + 1] = __halves2bfloat162(l2, l3);
        if (rp) rp[lane + j * 32] = e[j];
    }
}

// ============================ GEMM NT + fused softmax ========================
// logits = cls @ p^T (3-term). The last CTA per row-block (counter) runs the
// softmax for its 128 rows out of L2 and resets the counter.
__global__ void __launch_bounds__(256, 2)
gemm_nt(const __nv_bfloat16* __restrict__ Ah, const __nv_bfloat16* __restrict__ Al, int lda,
        const __nv_bfloat16* __restrict__ Bh, const __nv_bfloat16* __restrict__ Bl, int ldb,
        int Ksrc, float* __restrict__ C, int ldc,
        __nv_bfloat16* __restrict__ rh, __nv_bfloat16* __restrict__ rl,
        float* __restrict__ rf, int* __restrict__ cnt)
{
    extern __shared__ char smem[];
    const uint32_t sAb = smem_u32(smem);
    const uint32_t sBb = sAb + 3 * NT_STG;
    const int tid = threadIdx.x, lane = tid & 31, wid = tid >> 5;
    const int wm = wid >> 2, wn = wid & 3;
    const int bm = blockIdx.y * 128, bn = blockIdx.x * 128;

    float acc[4][4][4] = {};
    const int cpb = Ksrc / KC, nch = 3 * cpb;
    const int lrow = tid >> 2, lcb = (tid & 3) * 16;

    auto issue = [&](int c) {
        const int stg = c % 3;
        const int t = c / cpb;
        const size_t kk = (size_t)(c - t * cpb) * KC;
        const __nv_bfloat16* As = (t == 1) ? Al : Ah;
        const __nv_bfloat16* Bs = (t == 2) ? Bl : Bh;
        const uint32_t sa = sAb + stg * NT_STG, sb = sBb + stg * NT_STG;
#pragma unroll
        for (int it = 0; it < 2; ++it) {
            int row = lrow + it * 64;
            CP_ASYNC16(sa + row * 80 + lcb, As + (size_t)(bm + row) * lda + kk + lcb / 2);
            CP_ASYNC16(sb + row * 80 + lcb, Bs + (size_t)(bn + row) * ldb + kk + lcb / 2);
        }
        CP_COMMIT();
    };

    issue(0); issue(1);
    for (int c = 0; c < nch; ++c) {
        CP_WAIT1();
        __syncthreads();
        const int buf = c % 3;
        const uint32_t sa = sAb + buf * NT_STG, sb = sBb + buf * NT_STG;
#pragma unroll
        for (int kg = 0; kg < 2; ++kg) {
            const int kb = kg * 32;
            uint32_t a[4][4], bf[2][4];
#pragma unroll
            for (int mt = 0; mt < 4; ++mt) {
                uint32_t ad = sa + (uint32_t)(wm * 64 + mt * 16 + (lane & 15)) * 80
                            + kb + ((lane >> 4) << 4);
                LDSM_X4(a[mt][0], a[mt][1], a[mt][2], a[mt][3], ad);
            }
#pragma unroll
            for (int nh = 0; nh < 2; ++nh) {
                uint32_t bd = sb + (uint32_t)(wn * 32 + nh * 16 + ((lane >> 3) & 1) * 8 + (lane & 7)) * 80
                            + kb + ((lane >> 4) << 4);
                LDSM_X4(bf[nh][0], bf[nh][1], bf[nh][2], bf[nh][3], bd);
            }
#pragma unroll
            for (int nt = 0; nt < 4; ++nt) {
                const int nh = nt >> 1, lo = nt & 1;
                const uint32_t b0 = bf[nh][lo], b1 = bf[nh][lo + 2];
#pragma unroll
                for (int mt = 0; mt < 4; ++mt)
                    MMA16816(acc[mt][nt], a[mt], b0, b1);
            }
        }
        if (c + 2 < nch) issue(c + 2);
    }
    epilogue(acc, C, ldc, bm, bn, wm, wn, lane, nullptr);

    // ---- fused softmax: last CTA of this row-block processes 128 rows ----
    __shared__ int sflag;
    __syncthreads();
    if (tid == 0) {
        __threadfence();
        int old = atomicAdd(&cnt[blockIdx.y], 1);
        sflag = (old == (int)gridDim.x - 1) ? 1 : 0;
    }
    __syncthreads();
    if (sflag) {
        __threadfence();   // acquire: other CTAs' logits stores visible via L2
        for (int rr = wid; rr < 128; rr += 8) {
            const int row = bm + rr;
            softmax_row(C + (size_t)row * ldc,
                        rh + (size_t)row * Kp,
                        rl + (size_t)row * Kp,
                        rf ? rf + (size_t)row * Kp : nullptr, lane);
        }
        if (tid == 0) cnt[blockIdx.y] = 0;   // restore invariant for next launch
    }
}

// ============================ GEMM TT: parts[seg] = r^T @ cls (3-term) =======
__global__ void __launch_bounds__(256, 2)
gemm_tt(const __nv_bfloat16* __restrict__ Ah, const __nv_bfloat16* __restrict__ Al, int lda,
        const __nv_bfloat16* __restrict__ Bh, const __nv_bfloat16* __restrict__ Bl, int ldb,
        int Kslab, float* __restrict__ C, int ldc, size_t zstride)
{
    extern __shared__ char smem[];
    const uint32_t sRb = smem_u32(smem);
    const uint32_t sCb = sRb + 3 * TT_STG;
    const int tid = threadIdx.x, lane = tid & 31, wid = tid >> 5;
    const int wm = wid >> 2, wn = wid & 3;
    const int bm = blockIdx.y * 128, bn = blockIdx.x * 128;
    const int b0seg = blockIdx.z * Kslab;
    C += (size_t)blockIdx.z * zstride;

    float acc[4][4][4] = {};
    const int cpb = Kslab / KC, nch = 3 * cpb;
    const int lrow = tid >> 3, lc16 = (tid & 7) * 16;

    auto issue = [&](int c) {
        const int stg = c % 3;
        const int t = c / cpb;
        const int kk = (c - t * cpb) * KC;
        const __nv_bfloat16* As = (t == 1) ? Al : Ah;
        const __nv_bfloat16* Bs = (t == 2) ? Bl : Bh;
        const uint32_t sr = sRb + stg * TT_STG, sc = sCb + stg * TT_STG;
        const size_t gb = (size_t)(b0seg + kk + lrow);
        CP_ASYNC16(sr + lrow * 272 + lc16 * 2,      As + gb * lda + bm + lc16);
        CP_ASYNC16(sr + lrow * 272 + lc16 * 2 + 16, As + gb * lda + bm + lc16 + 8);
        CP_ASYNC16(sc + lrow * 272 + lc16 * 2,      Bs + gb * ldb + bn + lc16);
        CP_ASYNC16(sc + lrow * 272 + lc16 * 2 + 16, Bs + gb * ldb + bn + lc16 + 8);
        CP_COMMIT();
    };

    issue(0); issue(1);
    for (int c = 0; c < nch; ++c) {
        CP_WAIT1();
        __syncthreads();
        const int buf = c % 3;
        const uint32_t sr = sRb + buf * TT_STG, sc = sCb + buf * TT_STG;
#pragma unroll
        for (int kg = 0; kg < 2; ++kg) {
            uint32_t a[4][4], bf[2][4];
#pragma unroll
            for (int mt = 0; mt < 4; ++mt) {
                uint32_t ad = sr + (uint32_t)(kg * 16 + ((lane >> 4) << 3) + (lane & 7)) * 272
                            + (uint32_t)(wm * 64 + mt * 16 + ((lane >> 3) & 1) * 8) * 2;
                LDSM_X4T(a[mt][0], a[mt][1], a[mt][2], a[mt][3], ad);
            }
#pragma unroll
            for (int nh = 0; nh < 2; ++nh) {
                uint32_t bd = sc + (uint32_t)(kg * 16 + ((lane >> 3) & 1) * 8 + (lane & 7)) * 272
                            + (uint32_t)(wn * 32 + nh * 16 + ((lane >> 4) << 3)) * 2;
                LDSM_X4T(bf[nh][0], bf[nh][1], bf[nh][2], bf[nh][3], bd);
            }
#pragma unroll
            for (int nt = 0; nt < 4; ++nt) {
                const int nh = nt >> 1, w = nt & 1;
                const uint32_t b0 = bf[nh][w * 2], b1 = bf[nh][w * 2 + 1];
#pragma unroll
                for (int mt = 0; mt < 4; ++mt)
                    MMA16816(acc[mt][nt], a[mt], b0, b1);
            }
        }
        if (c + 2 < nch) issue(c + 2);
    }
    epilogue(acc, C, ldc, bm, bn, wm, wn, lane, nullptr);
}

// ============================ GEMM NN (1-term): z = r_h @ p_h + cls ==========
__global__ void __launch_bounds__(256, 2)
gemm_nn(const __nv_bfloat16* __restrict__ Ah, int lda,
        const __nv_bfloat16* __restrict__ Bh, int ldb,
        int Ksrc, float* __restrict__ C, int ldc, const float* __restrict__ addsrc)
{
    extern __shared__ char smem[];
    const uint32_t sAb = smem_u32(smem);
    const uint32_t sBb = sAb + 3 * NT_STG;
    const int tid = threadIdx.x, lane = tid & 31, wid = tid >> 5;
    const int wm = wid >> 2, wn = wid & 3;
    const int bm = blockIdx.y * 128, bn = blockIdx.x * 128;

    float acc[4][4][4] = {};
    const int nch = Ksrc / KC;
    const int lrow = tid >> 2, lcb = (tid & 3) * 16;
    const int trow = tid >> 3, tc16 = (tid & 7) * 16;

    auto issue = [&](int c) {
        const int stg = c % 3;
        const int kk = c * KC;
        const uint32_t sa = sAb + stg * NT_STG, sb = sBb + stg * TT_STG;
#pragma unroll
        for (int it = 0; it < 2; ++it) {
            int row = lrow + it * 64;
            CP_ASYNC16(sa + row * 80 + lcb, Ah + (size_t)(bm + row) * lda + kk + lcb / 2);
        }
        CP_ASYNC16(sb + trow * 272 + tc16 * 2,      Bh + (size_t)(kk + trow) * ldb + bn + tc16);
        CP_ASYNC16(sb + trow * 272 + tc16 * 2 + 16, Bh + (size_t)(kk + trow) * ldb + bn + tc16 + 8);
        CP_COMMIT();
    };

    issue(0); issue(1);
    for (int c = 0; c < nch; ++c) {
        CP_WAIT1();
        __syncthreads();
        const int buf = c % 3;
        const uint32_t sa = sAb + buf * NT_STG, sb = sBb + buf * TT_STG;
#pragma unroll
        for (int kg = 0; kg < 2; ++kg) {
            const int kb = kg * 32;
            uint32_t a[4][4], bf[2][4];
#pragma unroll
            for (int mt = 0; mt < 4; ++mt) {
                uint32_t ad = sa + (uint32_t)(wm * 64 + mt * 16 + (lane & 15)) * 80
                            + kb + ((lane >> 4) << 4);
                LDSM_X4(a[mt][0], a[mt][1], a[mt][2], a[mt][3], ad);
            }
#pragma unroll
            for (int nh = 0; nh < 2; ++nh) {
                uint32_t bd = sb + (uint32_t)(kg * 16 + ((lane >> 3) & 1) * 8 + (lane & 7)) * 272
                            + (uint32_t)(wn * 32 + nh * 16 + ((lane >> 4) << 3)) * 2;
                LDSM_X4T(bf[nh][0], bf[nh][1], bf[nh][2], bf[nh][3], bd);
            }
#pragma unroll
            for (int nt = 0; nt < 4; ++nt) {
                const int nh = nt >> 1, w = nt & 1;
                const uint32_t b0 = bf[nh][w * 2], b1 = bf[nh][w * 2 + 1];
#pragma unroll
                for (int mt = 0; mt < 4; ++mt)
                    MMA16816(acc[mt][nt], a[mt], b0, b1);
            }
        }
        if (c + 2 < nch) issue(c + 2);
    }
    epilogue(acc, C, ldc, bm, bn, wm, wn, lane, addsrc);
}

// ============================ split fp32 -> bf16 hi/lo =======================
__global__ void __launch_bounds__(256)
split_f32(const float* __restrict__ x, __nv_bfloat16* __restrict__ h,
          __nv_bfloat16* __restrict__ l, int n)
{
    int i = (blockIdx.x * 256 + threadIdx.x) * 4;
    if (i >= n) return;
    float4 v = *(const float4*)(x + i);
    __nv_bfloat16 h0 = __float2bfloat16(v.x), h1 = __float2bfloat16(v.y);
    __nv_bfloat16 h2 = __float2bfloat16(v.z), h3 = __float2bfloat16(v.w);
    __nv_bfloat16 l0 = __float2bfloat16(v.x - __bfloat162float(h0));
    __nv_bfloat16 l1 = __float2bfloat16(v.y - __bfloat162float(h1));
    __nv_bfloat16 l2 = __float2bfloat16(v.z - __bfloat162float(h2));
    __nv_bfloat16 l3 = __float2bfloat16(v.w - __bfloat162float(h3));
    ((__nv_bfloat162*)(h + i))[0] = __halves2bfloat162(h0, h1);
    ((__nv_bfloat162*)(h + i))[1] = __halves2bfloat162(h2, h3);
    ((__nv_bfloat162*)(l + i))[0] = __halves2bfloat162(l0, l1);
    ((__nv_bfloat162*)(l + i))[1] = __halves2bfloat162(l2, l3);
}

// ============================ reduce split-K + L2 normalize (vectorized) =====
__global__ void __launch_bounds__(256)
reduce_norm(const float* __restrict__ parts, __nv_bfloat16* __restrict__ ph,
            __nv_bfloat16* __restrict__ pl)
{
    const int k = blockIdx.x;
    const int tid = threadIdx.x;
    __shared__ float4 buf[Dd / 4];
    __shared__ float wred[8];
    __shared__ float sden;

    float4 s = make_float4(0.f, 0.f, 0.f, 0.f);
#pragma unroll
    for (int g = 0; g < SEG; ++g) {
        const float4 v = *(const float4*)(parts + (size_t)g * Kp * Dd + (size_t)k * Dd + tid * 4);
        s.x += v.x; s.y += v.y; s.z += v.z; s.w += v.w;
    }
    buf[tid] = s;
    float sq = s.x * s.x + s.y * s.y + s.z * s.z + s.w * s.w;
#pragma unroll
    for (int o = 16; o; o >>= 1) sq += __shfl_xor_sync(0xffffffffu, sq, o);
    if ((tid & 31) == 0) wred[tid >> 5] = sq;
    __syncthreads();
    if (tid == 0) {
        float t = 0.f;
#pragma unroll
        for (int i = 0; i < 8; ++i) t += wred[i];
        sden = sqrtf(t) + 1e-6f;
    }
    __syncthreads();
    const float inv = 1.0f / sden;
    const float4 b = buf[tid];
    float x0 = b.x * inv, x1 = b.y * inv, x2 = b.z * inv, x3 = b.w * inv;
    __nv_bfloat16 h0 = __float2bfloat16(x0), h1 = __float2bfloat16(x1);
    __nv_bfloat16 h2 = __float2bfloat16(x2), h3 = __float2bfloat16(x3);
    __nv_bfloat16 l0 = __float2bfloat16(x0 - __bfloat162float(h0));
    __nv_bfloat16 l1 = __float2bfloat16(x1 - __bfloat162float(h1));
    __nv_bfloat16 l2 = __float2bfloat16(x2 - __bfloat162float(h2));
    __nv_bfloat16 l3 = __float2bfloat16(x3 - __bfloat162float(h3));
    __nv_bfloat162* hp = (__nv_bfloat162*)(ph + (size_t)k * Dd + tid * 4);
    __nv_bfloat162* lp = (__nv_bfloat162*)(pl + (size_t)k * Dd + tid * 4);
    hp[0] = __halves2bfloat162(h0, h1);
    hp[1] = __halves2bfloat162(h2, h3);
    lp[0] = __halves2bfloat162(l0, l1);
    lp[1] = __halves2bfloat162(l2, l3);
}

// ============================ launcher =======================================
extern "C" void kernel_launch(void* const* d_in, const int* in_sizes, int n_in,
                              void* d_out, int out_size)
{
    const float* cls   = (const float*)d_in[0];
    const float* proto = (const float*)d_in[1];
    if (n_in >= 2 && in_sizes[0] < in_sizes[1]) {
        const float* t = cls; cls = proto; proto = t;
    }

    __nv_bfloat16 *cls_h, *cls_l, *p_h, *p_l, *r_h, *r_l;
    float *logits, *parts;
    int* cnt;
    cudaGetSymbolAddress((void**)&cls_h,  g_cls_h);
    cudaGetSymbolAddress((void**)&cls_l,  g_cls_l);
    cudaGetSymbolAddress((void**)&p_h,    g_p_h);
    cudaGetSymbolAddress((void**)&p_l,    g_p_l);
    cudaGetSymbolAddress((void**)&r_h,    g_r_h);
    cudaGetSymbolAddress((void**)&r_l,    g_r_l);
    cudaGetSymbolAddress((void**)&logits, g_logits);
    cudaGetSymbolAddress((void**)&parts,  g_parts);
    cudaGetSymbolAddress((void**)&cnt,    g_cnt);

    cudaFuncSetAttribute(gemm_nt, cudaFuncAttributeMaxDynamicSharedMemorySize, SMEM_NT);
    cudaFuncSetAttribute(gemm_tt, cudaFuncAttributeMaxDynamicSharedMemorySize, SMEM_TT);
    cudaFuncSetAttribute(gemm_nn, cudaFuncAttributeMaxDynamicSharedMemorySize, SMEM_NN);

    float* r_out = (float*)d_out;                          // [Bq, Kp]
    float* z_out = (float*)d_out + (size_t)Bq * Kp;        // [Bq, Dd]

    split_f32<<<(Bq * Dd) / 1024, 256>>>(cls, cls_h, cls_l, Bq * Dd);
    split_f32<<<(Kp * Dd) / 1024, 256>>>(proto, p_h, p_l, Kp * Dd);

    dim3 g1(Kp / 128, Bq / 128);         // (4, 64)
    dim3 g2(Dd / 128, Kp / 128, SEG);    // (8, 4, 8)
    dim3 g3(Dd / 128, Bq / 128);         // (8, 64)

    for (int s = 0; s < STAGES; ++s) {
        gemm_nt<<<g1, 256, SMEM_NT>>>(cls_h, cls_l, Dd, p_h, p_l, Dd,
                                      Dd, logits, Kp, r_h, r_l, nullptr, cnt);
        gemm_tt<<<g2, 256, SMEM_TT>>>(r_h, r_l, Kp, cls_h, cls_l, Dd,
                                      Bq / SEG, parts, Dd, (size_t)Kp * Dd);
        reduce_norm<<<Kp, 256>>>(parts, p_h, p_l);
    }

    gemm_nt<<<g1, 256, SMEM_NT>>>(cls_h, cls_l, Dd, p_h, p_l, Dd,
                                  Dd, logits, Kp, r_h, r_l, r_out, cnt);
    gemm_nn<<<g3, 256, SMEM_NN>>>(r_h, Kp, p_h, Dd,
                                  Kp, z_out, Dd, cls);
}

// round 12
// speedup vs baseline: 1.0259x; 1.0259x over previous
#include <cuda_runtime.h>
#include <cuda_bf16.h>
#include <cstdint>
#include <math.h>

#define Bq 8192
#define Dd 1024
#define Kp 512
#define SEG 8
#define STAGES 5

// ============================ device globals (no allocs allowed) ============
__device__ __align__(16) __nv_bfloat16 g_cls_h[(size_t)Bq * Dd];
__device__ __align__(16) __nv_bfloat16 g_cls_l[(size_t)Bq * Dd];
__device__ __align__(16) __nv_bfloat16 g_p_h[(size_t)Kp * Dd];
__device__ __align__(16) __nv_bfloat16 g_p_l[(size_t)Kp * Dd];
__device__ __align__(16) __nv_bfloat16 g_r_h[(size_t)Bq * Kp];
__device__ __align__(16) __nv_bfloat16 g_r_l[(size_t)Bq * Kp];
__device__ __align__(16) float g_logits[(size_t)Bq * Kp];
__device__ __align__(16) float g_parts[(size_t)SEG * Kp * Dd];

// ============================ PTX helpers (base sm_103-safe) =================
__device__ __forceinline__ uint32_t smem_u32(const void* p) {
    uint32_t a;
    asm("{ .reg .u64 t; cvta.to.shared.u64 t, %1; cvt.u32.u64 %0, t; }" : "=r"(a) : "l"(p));
    return a;
}
#define CP_ASYNC16(sa, gp) \
    asm volatile("cp.async.cg.shared.global [%0], [%1], 16;" :: "r"(sa), "l"(gp))
#define CP_COMMIT() asm volatile("cp.async.commit_group;")
#define CP_WAIT2()  asm volatile("cp.async.wait_group 2;")
#define CP_WAIT1()  asm volatile("cp.async.wait_group 1;")
#define LDSM_X4(r0, r1, r2, r3, addr) \
    asm volatile("ldmatrix.sync.aligned.m8n8.x4.shared.b16 {%0,%1,%2,%3}, [%4];" \
        : "=r"(r0), "=r"(r1), "=r"(r2), "=r"(r3) : "r"(addr))
#define LDSM_X4T(r0, r1, r2, r3, addr) \
    asm volatile("ldmatrix.sync.aligned.m8n8.x4.trans.shared.b16 {%0,%1,%2,%3}, [%4];" \
        : "=r"(r0), "=r"(r1), "=r"(r2), "=r"(r3) : "r"(addr))
#define MMA16816(d, a, b0v, b1v) \
    asm volatile("mma.sync.aligned.m16n8k16.row.col.f32.bf16.bf16.f32 " \
        "{%0,%1,%2,%3}, {%4,%5,%6,%7}, {%8,%9}, {%0,%1,%2,%3};" \
        : "+f"((d)[0]), "+f"((d)[1]), "+f"((d)[2]), "+f"((d)[3]) \
        : "r"((a)[0]), "r"((a)[1]), "r"((a)[2]), "r"((a)[3]), "r"(b0v), "r"(b1v))

// Tiles: CTA 128x128, 8 warps (2x4), warp 64x32, 4x4 of m16n8, KC=32, 3 stages.
#define KC 32
#define SROW 40
#define TROW 136
#define NT_STG (128 * SROW * 2)        // 10240 B
#define TT_STG (KC * TROW * 2)         // 8704 B
#define SMEM_NT (6 * NT_STG)           // 61440
#define SMEM_TT (6 * TT_STG)           // 52224
#define SMEM_NN (3 * NT_STG + 3 * TT_STG)  // 56832

// ---------------- shared epilogue ----------------
__device__ __forceinline__ void epilogue(float acc[4][4][4], float* C, int ldc,
                                         int bm, int bn, int wm, int wn, int lane,
                                         const float* addsrc)
{
#pragma unroll
    for (int mt = 0; mt < 4; ++mt) {
        const int r0 = bm + wm * 64 + mt * 16 + (lane >> 2);
#pragma unroll
        for (int nt = 0; nt < 4; ++nt) {
            const int col = bn + wn * 32 + nt * 8 + (lane & 3) * 2;
            float2 v0 = make_float2(acc[mt][nt][0], acc[mt][nt][1]);
            float2 v1 = make_float2(acc[mt][nt][2], acc[mt][nt][3]);
            if (addsrc) {
                const float2 a0 = *(const float2*)(addsrc + (size_t)r0 * ldc + col);
                const float2 a1 = *(const float2*)(addsrc + (size_t)(r0 + 8) * ldc + col);
                v0.x += a0.x; v0.y += a0.y;
                v1.x += a1.x; v1.y += a1.y;
            }
            *(float2*)(C + (size_t)r0 * ldc + col) = v0;
            *(float2*)(C + (size_t)(r0 + 8) * ldc + col) = v1;
        }
    }
}

// ============================ GEMM NT: logits = cls @ p^T (3-term) ===========
// Issue of chunk c+2 is hoisted to right after the barrier: buffer (c+2)%3
// held chunk c-1, whose compute all warps finished before this barrier.
__global__ void __launch_bounds__(256, 2)
gemm_nt(const __nv_bfloat16* __restrict__ Ah, const __nv_bfloat16* __restrict__ Al, int lda,
        const __nv_bfloat16* __restrict__ Bh, const __nv_bfloat16* __restrict__ Bl, int ldb,
        int Ksrc, float* __restrict__ C, int ldc)
{
    extern __shared__ char smem[];
    const uint32_t sAb = smem_u32(smem);
    const uint32_t sBb = sAb + 3 * NT_STG;
    const int tid = threadIdx.x, lane = tid & 31, wid = tid >> 5;
    const int wm = wid >> 2, wn = wid & 3;
    const int bm = blockIdx.y * 128, bn = blockIdx.x * 128;

    float acc[4][4][4] = {};
    const int cpb = Ksrc / KC, nch = 3 * cpb;
    const int lrow = tid >> 2, lcb = (tid & 3) * 16;

    auto issue = [&](int c) {
        const int stg = c % 3;
        const int t = c / cpb;
        const size_t kk = (size_t)(c - t * cpb) * KC;
        const __nv_bfloat16* As = (t == 1) ? Al : Ah;
        const __nv_bfloat16* Bs = (t == 2) ? Bl : Bh;
        const uint32_t sa = sAb + stg * NT_STG, sb = sBb + stg * NT_STG;
#pragma unroll
        for (int it = 0; it < 2; ++it) {
            int row = lrow + it * 64;
            CP_ASYNC16(sa + row * 80 + lcb, As + (size_t)(bm + row) * lda + kk + lcb / 2);
            CP_ASYNC16(sb + row * 80 + lcb, Bs + (size_t)(bn + row) * ldb + kk + lcb / 2);
        }
        CP_COMMIT();
    };

    issue(0); issue(1);
    for (int c = 0; c < nch; ++c) {
        CP_WAIT1();
        __syncthreads();
        if (c + 2 < nch) { issue(c + 2); }   // hoisted: buf (c+2)%3 is free here
        const int buf = c % 3;
        const uint32_t sa = sAb + buf * NT_STG, sb = sBb + buf * NT_STG;
#pragma unroll
        for (int kg = 0; kg < 2; ++kg) {
            const int kb = kg * 32;
            uint32_t a[4][4], bf[2][4];
#pragma unroll
            for (int mt = 0; mt < 4; ++mt) {
                uint32_t ad = sa + (uint32_t)(wm * 64 + mt * 16 + (lane & 15)) * 80
                            + kb + ((lane >> 4) << 4);
                LDSM_X4(a[mt][0], a[mt][1], a[mt][2], a[mt][3], ad);
            }
#pragma unroll
            for (int nh = 0; nh < 2; ++nh) {
                uint32_t bd = sb + (uint32_t)(wn * 32 + nh * 16 + ((lane >> 3) & 1) * 8 + (lane & 7)) * 80
                            + kb + ((lane >> 4) << 4);
                LDSM_X4(bf[nh][0], bf[nh][1], bf[nh][2], bf[nh][3], bd);
            }
#pragma unroll
            for (int nt = 0; nt < 4; ++nt) {
                const int nh = nt >> 1, lo = nt & 1;
                const uint32_t b0 = bf[nh][lo], b1 = bf[nh][lo + 2];
#pragma unroll
                for (int mt = 0; mt < 4; ++mt)
                    MMA16816(acc[mt][nt], a[mt], b0, b1);
            }
        }
    }
    epilogue(acc, C, ldc, bm, bn, wm, wn, lane, nullptr);
}

// ============================ GEMM TT: parts[seg] = r^T @ cls (3-term) =======
__global__ void __launch_bounds__(256, 2)
gemm_tt(const __nv_bfloat16* __restrict__ Ah, const __nv_bfloat16* __restrict__ Al, int lda,
        const __nv_bfloat16* __restrict__ Bh, const __nv_bfloat16* __restrict__ Bl, int ldb,
        int Kslab, float* __restrict__ C, int ldc, size_t zstride)
{
    extern __shared__ char smem[];
    const uint32_t sRb = smem_u32(smem);
    const uint32_t sCb = sRb + 3 * TT_STG;
    const int tid = threadIdx.x, lane = tid & 31, wid = tid >> 5;
    const int wm = wid >> 2, wn = wid & 3;
    const int bm = blockIdx.y * 128, bn = blockIdx.x * 128;
    const int b0seg = blockIdx.z * Kslab;
    C += (size_t)blockIdx.z * zstride;

    float acc[4][4][4] = {};
    const int cpb = Kslab / KC, nch = 3 * cpb;
    const int lrow = tid >> 3, lc16 = (tid & 7) * 16;

    auto issue = [&](int c) {
        const int stg = c % 3;
        const int t = c / cpb;
        const int kk = (c - t * cpb) * KC;
        const __nv_bfloat16* As = (t == 1) ? Al : Ah;
        const __nv_bfloat16* Bs = (t == 2) ? Bl : Bh;
        const uint32_t sr = sRb + stg * TT_STG, sc = sCb + stg * TT_STG;
        const size_t gb = (size_t)(b0seg + kk + lrow);
        CP_ASYNC16(sr + lrow * 272 + lc16 * 2,      As + gb * lda + bm + lc16);
        CP_ASYNC16(sr + lrow * 272 + lc16 * 2 + 16, As + gb * lda + bm + lc16 + 8);
        CP_ASYNC16(sc + lrow * 272 + lc16 * 2,      Bs + gb * ldb + bn + lc16);
        CP_ASYNC16(sc + lrow * 272 + lc16 * 2 + 16, Bs + gb * ldb + bn + lc16 + 8);
        CP_COMMIT();
    };

    issue(0); issue(1);
    for (int c = 0; c < nch; ++c) {
        CP_WAIT1();
        __syncthreads();
        if (c + 2 < nch) { issue(c + 2); }
        const int buf = c % 3;
        const uint32_t sr = sRb + buf * TT_STG, sc = sCb + buf * TT_STG;
#pragma unroll
        for (int kg = 0; kg < 2; ++kg) {
            uint32_t a[4][4], bf[2][4];
#pragma unroll
            for (int mt = 0; mt < 4; ++mt) {
                uint32_t ad = sr + (uint32_t)(kg * 16 + ((lane >> 4) << 3) + (lane & 7)) * 272
                            + (uint32_t)(wm * 64 + mt * 16 + ((lane >> 3) & 1) * 8) * 2;
                LDSM_X4T(a[mt][0], a[mt][1], a[mt][2], a[mt][3], ad);
            }
#pragma unroll
            for (int nh = 0; nh < 2; ++nh) {
                uint32_t bd = sc + (uint32_t)(kg * 16 + ((lane >> 3) & 1) * 8 + (lane & 7)) * 272
                            + (uint32_t)(wn * 32 + nh * 16 + ((lane >> 4) << 3)) * 2;
                LDSM_X4T(bf[nh][0], bf[nh][1], bf[nh][2], bf[nh][3], bd);
            }
#pragma unroll
            for (int nt = 0; nt < 4; ++nt) {
                const int nh = nt >> 1, w = nt & 1;
                const uint32_t b0 = bf[nh][w * 2], b1 = bf[nh][w * 2 + 1];
#pragma unroll
                for (int mt = 0; mt < 4; ++mt)
                    MMA16816(acc[mt][nt], a[mt], b0, b1);
            }
        }
    }
    epilogue(acc, C, ldc, bm, bn, wm, wn, lane, nullptr);
}

// ============================ GEMM NN (1-term): z = r_h @ p_h + cls ==========
__global__ void __launch_bounds__(256, 2)
gemm_nn(const __nv_bfloat16* __restrict__ Ah, int lda,
        const __nv_bfloat16* __restrict__ Bh, int ldb,
        int Ksrc, float* __restrict__ C, int ldc, const float* __restrict__ addsrc)
{
    extern __shared__ char smem[];
    const uint32_t sAb = smem_u32(smem);
    const uint32_t sBb = sAb + 3 * NT_STG;
    const int tid = threadIdx.x, lane = tid & 31, wid = tid >> 5;
    const int wm = wid >> 2, wn = wid & 3;
    const int bm = blockIdx.y * 128, bn = blockIdx.x * 128;

    float acc[4][4][4] = {};
    const int nch = Ksrc / KC;
    const int lrow = tid >> 2, lcb = (tid & 3) * 16;
    const int trow = tid >> 3, tc16 = (tid & 7) * 16;

    auto issue = [&](int c) {
        const int stg = c % 3;
        const int kk = c * KC;
        const uint32_t sa = sAb + stg * NT_STG, sb = sBb + stg * TT_STG;
#pragma unroll
        for (int it = 0; it < 2; ++it) {
            int row = lrow + it * 64;
            CP_ASYNC16(sa + row * 80 + lcb, Ah + (size_t)(bm + row) * lda + kk + lcb / 2);
        }
        CP_ASYNC16(sb + trow * 272 + tc16 * 2,      Bh + (size_t)(kk + trow) * ldb + bn + tc16);
        CP_ASYNC16(sb + trow * 272 + tc16 * 2 + 16, Bh + (size_t)(kk + trow) * ldb + bn + tc16 + 8);
        CP_COMMIT();
    };

    issue(0); issue(1);
    for (int c = 0; c < nch; ++c) {
        CP_WAIT1();
        __syncthreads();
        if (c + 2 < nch) { issue(c + 2); }
        const int buf = c % 3;
        const uint32_t sa = sAb + buf * NT_STG, sb = sBb + buf * TT_STG;
#pragma unroll
        for (int kg = 0; kg < 2; ++kg) {
            const int kb = kg * 32;
            uint32_t a[4][4], bf[2][4];
#pragma unroll
            for (int mt = 0; mt < 4; ++mt) {
                uint32_t ad = sa + (uint32_t)(wm * 64 + mt * 16 + (lane & 15)) * 80
                            + kb + ((lane >> 4) << 4);
                LDSM_X4(a[mt][0], a[mt][1], a[mt][2], a[mt][3], ad);
            }
#pragma unroll
            for (int nh = 0; nh < 2; ++nh) {
                uint32_t bd = sb + (uint32_t)(kg * 16 + ((lane >> 3) & 1) * 8 + (lane & 7)) * 272
                            + (uint32_t)(wn * 32 + nh * 16 + ((lane >> 4) << 3)) * 2;
                LDSM_X4T(bf[nh][0], bf[nh][1], bf[nh][2], bf[nh][3], bd);
            }
#pragma unroll
            for (int nt = 0; nt < 4; ++nt) {
                const int nh = nt >> 1, w = nt & 1;
                const uint32_t b0 = bf[nh][w * 2], b1 = bf[nh][w * 2 + 1];
#pragma unroll
                for (int mt = 0; mt < 4; ++mt)
                    MMA16816(acc[mt][nt], a[mt], b0, b1);
            }
        }
    }
    epilogue(acc, C, ldc, bm, bn, wm, wn, lane, addsrc);
}

// ============================ split fp32 -> bf16 hi/lo =======================
__global__ void __launch_bounds__(256)
split_f32(const float* __restrict__ x, __nv_bfloat16* __restrict__ h,
          __nv_bfloat16* __restrict__ l, int n)
{
    int i = (blockIdx.x * 256 + threadIdx.x) * 4;
    if (i >= n) return;
    float4 v = *(const float4*)(x + i);
    __nv_bfloat16 h0 = __float2bfloat16(v.x), h1 = __float2bfloat16(v.y);
    __nv_bfloat16 h2 = __float2bfloat16(v.z), h3 = __float2bfloat16(v.w);
    __nv_bfloat16 l0 = __float2bfloat16(v.x - __bfloat162float(h0));
    __nv_bfloat16 l1 = __float2bfloat16(v.y - __bfloat162float(h1));
    __nv_bfloat16 l2 = __float2bfloat16(v.z - __bfloat162float(h2));
    __nv_bfloat16 l3 = __float2bfloat16(v.w - __bfloat162float(h3));
    ((__nv_bfloat162*)(h + i))[0] = __halves2bfloat162(h0, h1);
    ((__nv_bfloat162*)(h + i))[1] = __halves2bfloat162(h2, h3);
    ((__nv_bfloat162*)(l + i))[0] = __halves2bfloat162(l0, l1);
    ((__nv_bfloat162*)(l + i))[1] = __halves2bfloat162(l2, l3);
}

// ============================ softmax: one warp per 512-col row ==============
// Each lane owns 16 columns: 4x float4 at column (lane + j*32)*4, j=0..3.
__global__ void __launch_bounds__(256)
softmax_warp(const float* __restrict__ L, __nv_bfloat16* __restrict__ rh,
             __nv_bfloat16* __restrict__ rl, float* __restrict__ rf)
{
    const int row = blockIdx.x * 8 + (threadIdx.x >> 5);
    const int lane = threadIdx.x & 31;
    const float4* Lr = (const float4*)(L + (size_t)row * Kp);

    float4 v[4];
#pragma unroll
    for (int j = 0; j < 4; ++j) v[j] = Lr[lane + j * 32];

    float m = -1e30f;
#pragma unroll
    for (int j = 0; j < 4; ++j)
        m = fmaxf(m, fmaxf(fmaxf(v[j].x, v[j].y), fmaxf(v[j].z, v[j].w)));
#pragma unroll
    for (int o = 16; o; o >>= 1) m = fmaxf(m, __shfl_xor_sync(0xffffffffu, m, o));

    float4 e[4];
    float s = 0.f;
#pragma unroll
    for (int j = 0; j < 4; ++j) {
        e[j].x = __expf(v[j].x - m); e[j].y = __expf(v[j].y - m);
        e[j].z = __expf(v[j].z - m); e[j].w = __expf(v[j].w - m);
        s += (e[j].x + e[j].y) + (e[j].z + e[j].w);
    }
#pragma unroll
    for (int o = 16; o; o >>= 1) s += __shfl_xor_sync(0xffffffffu, s, o);

    const float inv = 1.0f / s;
    __nv_bfloat162* hp = (__nv_bfloat162*)(rh + (size_t)row * Kp);
    __nv_bfloat162* lp = (__nv_bfloat162*)(rl + (size_t)row * Kp);
    float4* rp = rf ? (float4*)(rf + (size_t)row * Kp) : nullptr;
#pragma unroll
    for (int j = 0; j < 4; ++j) {
        e[j].x *= inv; e[j].y *= inv; e[j].z *= inv; e[j].w *= inv;
        __nv_bfloat16 h0 = __float2bfloat16(e[j].x), h1 = __float2bfloat16(e[j].y);
        __nv_bfloat16 h2 = __float2bfloat16(e[j].z), h3 = __float2bfloat16(e[j].w);
        __nv_bfloat16 l0 = __float2bfloat16(e[j].x - __bfloat162float(h0));
        __nv_bfloat16 l1 = __float2bfloat16(e[j].y - __bfloat162float(h1));
        __nv_bfloat16 l2 = __float2bfloat16(e[j].z - __bfloat162float(h2));
        __nv_bfloat16 l3 = __float2bfloat16(e[j].w - __bfloat162float(h3));
        const int c2 = (lane + j * 32) * 2;
        hp[c2 + 0] = __halves2bfloat162(h0, h1);
        hp[c2 + 1] = __halves2bfloat162(h2, h3);
        lp[c2 + 0] = __halves2bfloat162(l0, l1);
        lp[c2 + 1] = __halves2bfloat162(l2, l3);
        if (rp) rp[lane + j * 32] = e[j];
    }
}

// ============================ reduce split-K + L2 normalize (vectorized) =====
__global__ void __launch_bounds__(256)
reduce_norm(const float* __restrict__ parts, __nv_bfloat16* __restrict__ ph,
            __nv_bfloat16* __restrict__ pl)
{
    const int k = blockIdx.x;
    const int tid = threadIdx.x;
    __shared__ float4 buf[Dd / 4];
    __shared__ float wred[8];
    __shared__ float sden;

    float4 s = make_float4(0.f, 0.f, 0.f, 0.f);
#pragma unroll
    for (int g = 0; g < SEG; ++g) {
        const float4 v = *(const float4*)(parts + (size_t)g * Kp * Dd + (size_t)k * Dd + tid * 4);
        s.x += v.x; s.y += v.y; s.z += v.z; s.w += v.w;
    }
    buf[tid] = s;
    float sq = s.x * s.x + s.y * s.y + s.z * s.z + s.w * s.w;
#pragma unroll
    for (int o = 16; o; o >>= 1) sq += __shfl_xor_sync(0xffffffffu, sq, o);
    if ((tid & 31) == 0) wred[tid >> 5] = sq;
    __syncthreads();
    if (tid == 0) {
        float t = 0.f;
#pragma unroll
        for (int i = 0; i < 8; ++i) t += wred[i];
        sden = sqrtf(t) + 1e-6f;
    }
    __syncthreads();
    const float inv = 1.0f / sden;
    const float4 b = buf[tid];
    float x0 = b.x * inv, x1 = b.y * inv, x2 = b.z * inv, x3 = b.w * inv;
    __nv_bfloat16 h0 = __float2bfloat16(x0), h1 = __float2bfloat16(x1);
    __nv_bfloat16 h2 = __float2bfloat16(x2), h3 = __float2bfloat16(x3);
    __nv_bfloat16 l0 = __float2bfloat16(x0 - __bfloat162float(h0));
    __nv_bfloat16 l1 = __float2bfloat16(x1 - __bfloat162float(h1));
    __nv_bfloat16 l2 = __float2bfloat16(x2 - __bfloat162float(h2));
    __nv_bfloat16 l3 = __float2bfloat16(x3 - __bfloat162float(h3));
    __nv_bfloat162* hp = (__nv_bfloat162*)(ph + (size_t)k * Dd + tid * 4);
    __nv_bfloat162* lp = (__nv_bfloat162*)(pl + (size_t)k * Dd + tid * 4);
    hp[0] = __halves2bfloat162(h0, h1);
    hp[1] = __halves2bfloat162(h2, h3);
    lp[0] = __halves2bfloat162(l0, l1);
    lp[1] = __halves2bfloat162(l2, l3);
}

// ============================ launcher =======================================
extern "C" void kernel_launch(void* const* d_in, const int* in_sizes, int n_in,
                              void* d_out, int out_size)
{
    const float* cls   = (const float*)d_in[0];
    const float* proto = (const float*)d_in[1];
    if (n_in >= 2 && in_sizes[0] < in_sizes[1]) {
        const float* t = cls; cls = proto; proto = t;
    }

    __nv_bfloat16 *cls_h, *cls_l, *p_h, *p_l, *r_h, *r_l;
    float *logits, *parts;
    cudaGetSymbolAddress((void**)&cls_h,  g_cls_h);
    cudaGetSymbolAddress((void**)&cls_l,  g_cls_l);
    cudaGetSymbolAddress((void**)&p_h,    g_p_h);
    cudaGetSymbolAddress((void**)&p_l,    g_p_l);
    cudaGetSymbolAddress((void**)&r_h,    g_r_h);
    cudaGetSymbolAddress((void**)&r_l,    g_r_l);
    cudaGetSymbolAddress((void**)&logits, g_logits);
    cudaGetSymbolAddress((void**)&parts,  g_parts);

    cudaFuncSetAttribute(gemm_nt, cudaFuncAttributeMaxDynamicSharedMemorySize, SMEM_NT);
    cudaFuncSetAttribute(gemm_tt, cudaFuncAttributeMaxDynamicSharedMemorySize, SMEM_TT);
    cudaFuncSetAttribute(gemm_nn, cudaFuncAttributeMaxDynamicSharedMemorySize, SMEM_NN);

    float* r_out = (float*)d_out;                          // [Bq, Kp]
    float* z_out = (float*)d_out + (size_t)Bq * Kp;        // [Bq, Dd]

    split_f32<<<(Bq * Dd) / 1024, 256>>>(cls, cls_h, cls_l, Bq * Dd);
    split_f32<<<(Kp * Dd) / 1024, 256>>>(proto, p_h, p_l, Kp * Dd);

    dim3 g1(Kp / 128, Bq / 128);         // (4, 64)
    dim3 g2(Dd / 128, Kp / 128, SEG);    // (8, 4, 8)
    dim3 g3(Dd / 128, Bq / 128);         // (8, 64)

    for (int s = 0; s < STAGES; ++s) {
        gemm_nt<<<g1, 256, SMEM_NT>>>(cls_h, cls_l, Dd, p_h, p_l, Dd,
                                      Dd, logits, Kp);
        softmax_warp<<<Bq / 8, 256>>>(logits, r_h, r_l, nullptr);
        gemm_tt<<<g2, 256, SMEM_TT>>>(r_h, r_l, Kp, cls_h, cls_l, Dd,
                                      Bq / SEG, parts, Dd, (size_t)Kp * Dd);
        reduce_norm<<<Kp, 256>>>(parts, p_h, p_l);
    }

    gemm_nt<<<g1, 256, SMEM_NT>>>(cls_h, cls_l, Dd, p_h, p_l, Dd,
                                  Dd, logits, Kp);
    softmax_warp<<<Bq / 8, 256>>>(logits, r_h, r_l, r_out);
    gemm_nn<<<g3, 256, SMEM_NN>>>(r_h, Kp, p_h, Dd,
                                  Kp, z_out, Dd, cls);
}

// round 13
// speedup vs baseline: 1.0528x; 1.0262x over previous
#include <cuda_runtime.h>
#include <cuda_bf16.h>
#include <cstdint>
#include <math.h>

#define Bq 8192
#define Dd 1024
#define Kp 512
#define SEG 8
#define STAGES 5

// ============================ device globals (no allocs allowed) ============
__device__ __align__(16) __nv_bfloat16 g_cls_h[(size_t)Bq * Dd];
__device__ __align__(16) __nv_bfloat16 g_cls_l[(size_t)Bq * Dd];
__device__ __align__(16) __nv_bfloat16 g_p_h[(size_t)Kp * Dd];
__device__ __align__(16) __nv_bfloat16 g_p_l[(size_t)Kp * Dd];
__device__ __align__(16) __nv_bfloat16 g_r_h[(size_t)Bq * Kp];
__device__ __align__(16) __nv_bfloat16 g_r_l[(size_t)Bq * Kp];
__device__ __align__(16) float g_logits[(size_t)Bq * Kp];
__device__ __align__(16) float g_parts[(size_t)SEG * Kp * Dd];

// ============================ PTX helpers (base sm_103-safe) =================
__device__ __forceinline__ uint32_t smem_u32(const void* p) {
    uint32_t a;
    asm("{ .reg .u64 t; cvta.to.shared.u64 t, %1; cvt.u32.u64 %0, t; }" : "=r"(a) : "l"(p));
    return a;
}
#define CP_ASYNC16(sa, gp) \
    asm volatile("cp.async.cg.shared.global [%0], [%1], 16;" :: "r"(sa), "l"(gp))
#define CP_COMMIT() asm volatile("cp.async.commit_group;")
#define CP_WAIT2()  asm volatile("cp.async.wait_group 2;")
#define LDSM_X4(r0, r1, r2, r3, addr) \
    asm volatile("ldmatrix.sync.aligned.m8n8.x4.shared.b16 {%0,%1,%2,%3}, [%4];" \
        : "=r"(r0), "=r"(r1), "=r"(r2), "=r"(r3) : "r"(addr))
#define LDSM_X4T(r0, r1, r2, r3, addr) \
    asm volatile("ldmatrix.sync.aligned.m8n8.x4.trans.shared.b16 {%0,%1,%2,%3}, [%4];" \
        : "=r"(r0), "=r"(r1), "=r"(r2), "=r"(r3) : "r"(addr))
#define MMA16816(d, a, b0v, b1v) \
    asm volatile("mma.sync.aligned.m16n8k16.row.col.f32.bf16.bf16.f32 " \
        "{%0,%1,%2,%3}, {%4,%5,%6,%7}, {%8,%9}, {%0,%1,%2,%3};" \
        : "+f"((d)[0]), "+f"((d)[1]), "+f"((d)[2]), "+f"((d)[3]) \
        : "r"((a)[0]), "r"((a)[1]), "r"((a)[2]), "r"((a)[3]), "r"(b0v), "r"(b1v))

// Tiles: CTA 128x128, 8 warps (2x4), warp 64x32, KC=32.
// 4 SMEM buffers, 3 cp.async groups in flight (depth-3 prefetch).
#define KC 32
#define SROW 40
#define TROW 136
#define NT_STG (128 * SROW * 2)        // 10240 B
#define TT_STG (KC * TROW * 2)         // 8704 B
#define SMEM_NT (8 * NT_STG)               // 81920
#define SMEM_TT (8 * TT_STG)               // 69632
#define SMEM_NN (4 * NT_STG + 4 * TT_STG)  // 75776

// ---------------- shared epilogue ----------------
__device__ __forceinline__ void epilogue(float acc[4][4][4], float* C, int ldc,
                                         int bm, int bn, int wm, int wn, int lane,
                                         const float* addsrc)
{
#pragma unroll
    for (int mt = 0; mt < 4; ++mt) {
        const int r0 = bm + wm * 64 + mt * 16 + (lane >> 2);
#pragma unroll
        for (int nt = 0; nt < 4; ++nt) {
            const int col = bn + wn * 32 + nt * 8 + (lane & 3) * 2;
            float2 v0 = make_float2(acc[mt][nt][0], acc[mt][nt][1]);
            float2 v1 = make_float2(acc[mt][nt][2], acc[mt][nt][3]);
            if (addsrc) {
                const float2 a0 = *(const float2*)(addsrc + (size_t)r0 * ldc + col);
                const float2 a1 = *(const float2*)(addsrc + (size_t)(r0 + 8) * ldc + col);
                v0.x += a0.x; v0.y += a0.y;
                v1.x += a1.x; v1.y += a1.y;
            }
            *(float2*)(C + (size_t)r0 * ldc + col) = v0;
            *(float2*)(C + (size_t)(r0 + 8) * ldc + col) = v1;
        }
    }
}

// ============================ GEMM NT: logits = cls @ p^T (3-term) ===========
// Ring safety: at iter c, issue(c+3) targets buf (c-1)&3; compute of chunk c-1
// finished in all warps before this iteration's barrier, which precedes issue.
__global__ void __launch_bounds__(256, 2)
gemm_nt(const __nv_bfloat16* __restrict__ Ah, const __nv_bfloat16* __restrict__ Al, int lda,
        const __nv_bfloat16* __restrict__ Bh, const __nv_bfloat16* __restrict__ Bl, int ldb,
        int Ksrc, float* __restrict__ C, int ldc)
{
    extern __shared__ char smem[];
    const uint32_t sAb = smem_u32(smem);
    const uint32_t sBb = sAb + 4 * NT_STG;
    const int tid = threadIdx.x, lane = tid & 31, wid = tid >> 5;
    const int wm = wid >> 2, wn = wid & 3;
    const int bm = blockIdx.y * 128, bn = blockIdx.x * 128;

    float acc[4][4][4] = {};
    const int cpb = Ksrc / KC, nch = 3 * cpb;
    const int lrow = tid >> 2, lcb = (tid & 3) * 16;

    auto issue = [&](int c) {
        const int stg = c & 3;
        const int t = c / cpb;
        const size_t kk = (size_t)(c - t * cpb) * KC;
        const __nv_bfloat16* As = (t == 1) ? Al : Ah;
        const __nv_bfloat16* Bs = (t == 2) ? Bl : Bh;
        const uint32_t sa = sAb + stg * NT_STG, sb = sBb + stg * NT_STG;
#pragma unroll
        for (int it = 0; it < 2; ++it) {
            int row = lrow + it * 64;
            CP_ASYNC16(sa + row * 80 + lcb, As + (size_t)(bm + row) * lda + kk + lcb / 2);
            CP_ASYNC16(sb + row * 80 + lcb, Bs + (size_t)(bn + row) * ldb + kk + lcb / 2);
        }
        CP_COMMIT();
    };

    issue(0); issue(1); issue(2);
    for (int c = 0; c < nch; ++c) {
        CP_WAIT2();
        __syncthreads();
        const int buf = c & 3;
        const uint32_t sa = sAb + buf * NT_STG, sb = sBb + buf * NT_STG;
#pragma unroll
        for (int kg = 0; kg < 2; ++kg) {
            const int kb = kg * 32;
            uint32_t a[4][4], bf[2][4];
#pragma unroll
            for (int mt = 0; mt < 4; ++mt) {
                uint32_t ad = sa + (uint32_t)(wm * 64 + mt * 16 + (lane & 15)) * 80
                            + kb + ((lane >> 4) << 4);
                LDSM_X4(a[mt][0], a[mt][1], a[mt][2], a[mt][3], ad);
            }
#pragma unroll
            for (int nh = 0; nh < 2; ++nh) {
                uint32_t bd = sb + (uint32_t)(wn * 32 + nh * 16 + ((lane >> 3) & 1) * 8 + (lane & 7)) * 80
                            + kb + ((lane >> 4) << 4);
                LDSM_X4(bf[nh][0], bf[nh][1], bf[nh][2], bf[nh][3], bd);
            }
#pragma unroll
            for (int nt = 0; nt < 4; ++nt) {
                const int nh = nt >> 1, lo = nt & 1;
                const uint32_t b0 = bf[nh][lo], b1 = bf[nh][lo + 2];
#pragma unroll
                for (int mt = 0; mt < 4; ++mt)
                    MMA16816(acc[mt][nt], a[mt], b0, b1);
            }
        }
        if (c + 3 < nch) issue(c + 3);
    }
    epilogue(acc, C, ldc, bm, bn, wm, wn, lane, nullptr);
}

// ============================ GEMM TT: parts[seg] = r^T @ cls (3-term) =======
__global__ void __launch_bounds__(256, 2)
gemm_tt(const __nv_bfloat16* __restrict__ Ah, const __nv_bfloat16* __restrict__ Al, int lda,
        const __nv_bfloat16* __restrict__ Bh, const __nv_bfloat16* __restrict__ Bl, int ldb,
        int Kslab, float* __restrict__ C, int ldc, size_t zstride)
{
    extern __shared__ char smem[];
    const uint32_t sRb = smem_u32(smem);
    const uint32_t sCb = sRb + 4 * TT_STG;
    const int tid = threadIdx.x, lane = tid & 31, wid = tid >> 5;
    const int wm = wid >> 2, wn = wid & 3;
    const int bm = blockIdx.y * 128, bn = blockIdx.x * 128;
    const int b0seg = blockIdx.z * Kslab;
    C += (size_t)blockIdx.z * zstride;

    float acc[4][4][4] = {};
    const int cpb = Kslab / KC, nch = 3 * cpb;
    const int lrow = tid >> 3, lc16 = (tid & 7) * 16;

    auto issue = [&](int c) {
        const int stg = c & 3;
        const int t = c / cpb;
        const int kk = (c - t * cpb) * KC;
        const __nv_bfloat16* As = (t == 1) ? Al : Ah;
        const __nv_bfloat16* Bs = (t == 2) ? Bl : Bh;
        const uint32_t sr = sRb + stg * TT_STG, sc = sCb + stg * TT_STG;
        const size_t gb = (size_t)(b0seg + kk + lrow);
        CP_ASYNC16(sr + lrow * 272 + lc16 * 2,      As + gb * lda + bm + lc16);
        CP_ASYNC16(sr + lrow * 272 + lc16 * 2 + 16, As + gb * lda + bm + lc16 + 8);
        CP_ASYNC16(sc + lrow * 272 + lc16 * 2,      Bs + gb * ldb + bn + lc16);
        CP_ASYNC16(sc + lrow * 272 + lc16 * 2 + 16, Bs + gb * ldb + bn + lc16 + 8);
        CP_COMMIT();
    };

    issue(0); issue(1); issue(2);
    for (int c = 0; c < nch; ++c) {
        CP_WAIT2();
        __syncthreads();
        const int buf = c & 3;
        const uint32_t sr = sRb + buf * TT_STG, sc = sCb + buf * TT_STG;
#pragma unroll
        for (int kg = 0; kg < 2; ++kg) {
            uint32_t a[4][4], bf[2][4];
#pragma unroll
            for (int mt = 0; mt < 4; ++mt) {
                uint32_t ad = sr + (uint32_t)(kg * 16 + ((lane >> 4) << 3) + (lane & 7)) * 272
                            + (uint32_t)(wm * 64 + mt * 16 + ((lane >> 3) & 1) * 8) * 2;
                LDSM_X4T(a[mt][0], a[mt][1], a[mt][2], a[mt][3], ad);
            }
#pragma unroll
            for (int nh = 0; nh < 2; ++nh) {
                uint32_t bd = sc + (uint32_t)(kg * 16 + ((lane >> 3) & 1) * 8 + (lane & 7)) * 272
                            + (uint32_t)(wn * 32 + nh * 16 + ((lane >> 4) << 3)) * 2;
                LDSM_X4T(bf[nh][0], bf[nh][1], bf[nh][2], bf[nh][3], bd);
            }
#pragma unroll
            for (int nt = 0; nt < 4; ++nt) {
                const int nh = nt >> 1, w = nt & 1;
                const uint32_t b0 = bf[nh][w * 2], b1 = bf[nh][w * 2 + 1];
#pragma unroll
                for (int mt = 0; mt < 4; ++mt)
                    MMA16816(acc[mt][nt], a[mt], b0, b1);
            }
        }
        if (c + 3 < nch) issue(c + 3);
    }
    epilogue(acc, C, ldc, bm, bn, wm, wn, lane, nullptr);
}

// ============================ GEMM NN (1-term): z = r_h @ p_h + cls ==========
__global__ void __launch_bounds__(256, 2)
gemm_nn(const __nv_bfloat16* __restrict__ Ah, int lda,
        const __nv_bfloat16* __restrict__ Bh, int ldb,
        int Ksrc, float* __restrict__ C, int ldc, const float* __restrict__ addsrc)
{
    extern __shared__ char smem[];
    const uint32_t sAb = smem_u32(smem);
    const uint32_t sBb = sAb + 4 * NT_STG;
    const int tid = threadIdx.x, lane = tid & 31, wid = tid >> 5;
    const int wm = wid >> 2, wn = wid & 3;
    const int bm = blockIdx.y * 128, bn = blockIdx.x * 128;

    float acc[4][4][4] = {};
    const int nch = Ksrc / KC;
    const int lrow = tid >> 2, lcb = (tid & 3) * 16;
    const int trow = tid >> 3, tc16 = (tid & 7) * 16;

    auto issue = [&](int c) {
        const int stg = c & 3;
        const int kk = c * KC;
        const uint32_t sa = sAb + stg * NT_STG, sb = sBb + stg * TT_STG;
#pragma unroll
        for (int it = 0; it < 2; ++it) {
            int row = lrow + it * 64;
            CP_ASYNC16(sa + row * 80 + lcb, Ah + (size_t)(bm + row) * lda + kk + lcb / 2);
        }
        CP_ASYNC16(sb + trow * 272 + tc16 * 2,      Bh + (size_t)(kk + trow) * ldb + bn + tc16);
        CP_ASYNC16(sb + trow * 272 + tc16 * 2 + 16, Bh + (size_t)(kk + trow) * ldb + bn + tc16 + 8);
        CP_COMMIT();
    };

    issue(0); issue(1); issue(2);
    for (int c = 0; c < nch; ++c) {
        CP_WAIT2();
        __syncthreads();
        const int buf = c & 3;
        const uint32_t sa = sAb + buf * NT_STG, sb = sBb + buf * TT_STG;
#pragma unroll
        for (int kg = 0; kg < 2; ++kg) {
            const int kb = kg * 32;
            uint32_t a[4][4], bf[2][4];
#pragma unroll
            for (int mt = 0; mt < 4; ++mt) {
                uint32_t ad = sa + (uint32_t)(wm * 64 + mt * 16 + (lane & 15)) * 80
                            + kb + ((lane >> 4) << 4);
                LDSM_X4(a[mt][0], a[mt][1], a[mt][2], a[mt][3], ad);
            }
#pragma unroll
            for (int nh = 0; nh < 2; ++nh) {
                uint32_t bd = sb + (uint32_t)(kg * 16 + ((lane >> 3) & 1) * 8 + (lane & 7)) * 272
                            + (uint32_t)(wn * 32 + nh * 16 + ((lane >> 4) << 3)) * 2;
                LDSM_X4T(bf[nh][0], bf[nh][1], bf[nh][2], bf[nh][3], bd);
            }
#pragma unroll
            for (int nt = 0; nt < 4; ++nt) {
                const int nh = nt >> 1, w = nt & 1;
                const uint32_t b0 = bf[nh][w * 2], b1 = bf[nh][w * 2 + 1];
#pragma unroll
                for (int mt = 0; mt < 4; ++mt)
                    MMA16816(acc[mt][nt], a[mt], b0, b1);
            }
        }
        if (c + 3 < nch) issue(c + 3);
    }
    epilogue(acc, C, ldc, bm, bn, wm, wn, lane, addsrc);
}

// ============================ split fp32 -> bf16 hi/lo =======================
__global__ void __launch_bounds__(256)
split_f32(const float* __restrict__ x, __nv_bfloat16* __restrict__ h,
          __nv_bfloat16* __restrict__ l, int n)
{
    int i = (blockIdx.x * 256 + threadIdx.x) * 4;
    if (i >= n) return;
    float4 v = *(const float4*)(x + i);
    __nv_bfloat16 h0 = __float2bfloat16(v.x), h1 = __float2bfloat16(v.y);
    __nv_bfloat16 h2 = __float2bfloat16(v.z), h3 = __float2bfloat16(v.w);
    __nv_bfloat16 l0 = __float2bfloat16(v.x - __bfloat162float(h0));
    __nv_bfloat16 l1 = __float2bfloat16(v.y - __bfloat162float(h1));
    __nv_bfloat16 l2 = __float2bfloat16(v.z - __bfloat162float(h2));
    __nv_bfloat16 l3 = __float2bfloat16(v.w - __bfloat162float(h3));
    ((__nv_bfloat162*)(h + i))[0] = __halves2bfloat162(h0, h1);
    ((__nv_bfloat162*)(h + i))[1] = __halves2bfloat162(h2, h3);
    ((__nv_bfloat162*)(l + i))[0] = __halves2bfloat162(l0, l1);
    ((__nv_bfloat162*)(l + i))[1] = __halves2bfloat162(l2, l3);
}

// ============================ softmax: one warp per 512-col row ==============
__global__ void __launch_bounds__(256)
softmax_warp(const float* __restrict__ L, __nv_bfloat16* __restrict__ rh,
             __nv_bfloat16* __restrict__ rl, float* __restrict__ rf)
{
    const int row = blockIdx.x * 8 + (threadIdx.x >> 5);
    const int lane = threadIdx.x & 31;
    const float4* Lr = (const float4*)(L + (size_t)row * Kp);

    float4 v[4];
#pragma unroll
    for (int j = 0; j < 4; ++j) v[j] = Lr[lane + j * 32];

    float m = -1e30f;
#pragma unroll
    for (int j = 0; j < 4; ++j)
        m = fmaxf(m, fmaxf(fmaxf(v[j].x, v[j].y), fmaxf(v[j].z, v[j].w)));
#pragma unroll
    for (int o = 16; o; o >>= 1) m = fmaxf(m, __shfl_xor_sync(0xffffffffu, m, o));

    float4 e[4];
    float s = 0.f;
#pragma unroll
    for (int j = 0; j < 4; ++j) {
        e[j].x = __expf(v[j].x - m); e[j].y = __expf(v[j].y - m);
        e[j].z = __expf(v[j].z - m); e[j].w = __expf(v[j].w - m);
        s += (e[j].x + e[j].y) + (e[j].z + e[j].w);
    }
#pragma unroll
    for (int o = 16; o; o >>= 1) s += __shfl_xor_sync(0xffffffffu, s, o);

    const float inv = 1.0f / s;
    __nv_bfloat162* hp = (__nv_bfloat162*)(rh + (size_t)row * Kp);
    __nv_bfloat162* lp = (__nv_bfloat162*)(rl + (size_t)row * Kp);
    float4* rp = rf ? (float4*)(rf + (size_t)row * Kp) : nullptr;
#pragma unroll
    for (int j = 0; j < 4; ++j) {
        e[j].x *= inv; e[j].y *= inv; e[j].z *= inv; e[j].w *= inv;
        __nv_bfloat16 h0 = __float2bfloat16(e[j].x), h1 = __float2bfloat16(e[j].y);
        __nv_bfloat16 h2 = __float2bfloat16(e[j].z), h3 = __float2bfloat16(e[j].w);
        __nv_bfloat16 l0 = __float2bfloat16(e[j].x - __bfloat162float(h0));
        __nv_bfloat16 l1 = __float2bfloat16(e[j].y - __bfloat162float(h1));
        __nv_bfloat16 l2 = __float2bfloat16(e[j].z - __bfloat162float(h2));
        __nv_bfloat16 l3 = __float2bfloat16(e[j].w - __bfloat162float(h3));
        const int c2 = (lane + j * 32) * 2;
        hp[c2 + 0] = __halves2bfloat162(h0, h1);
        hp[c2 + 1] = __halves2bfloat162(h2, h3);
        lp[c2 + 0] = __halves2bfloat162(l0, l1);
        lp[c2 + 1] = __halves2bfloat162(l2, l3);
        if (rp) rp[lane + j * 32] = e[j];
    }
}

// ============================ reduce split-K + L2 normalize (vectorized) =====
__global__ void __launch_bounds__(256)
reduce_norm(const float* __restrict__ parts, __nv_bfloat16* __restrict__ ph,
            __nv_bfloat16* __restrict__ pl)
{
    const int k = blockIdx.x;
    const int tid = threadIdx.x;
    __shared__ float4 buf[Dd / 4];
    __shared__ float wred[8];
    __shared__ float sden;

    float4 s = make_float4(0.f, 0.f, 0.f, 0.f);
#pragma unroll
    for (int g = 0; g < SEG; ++g) {
        const float4 v = *(const float4*)(parts + (size_t)g * Kp * Dd + (size_t)k * Dd + tid * 4);
        s.x += v.x; s.y += v.y; s.z += v.z; s.w += v.w;
    }
    buf[tid] = s;
    float sq = s.x * s.x + s.y * s.y + s.z * s.z + s.w * s.w;
#pragma unroll
    for (int o = 16; o; o >>= 1) sq += __shfl_xor_sync(0xffffffffu, sq, o);
    if ((tid & 31) == 0) wred[tid >> 5] = sq;
    __syncthreads();
    if (tid == 0) {
        float t = 0.f;
#pragma unroll
        for (int i = 0; i < 8; ++i) t += wred[i];
        sden = sqrtf(t) + 1e-6f;
    }
    __syncthreads();
    const float inv = 1.0f / sden;
    const float4 b = buf[tid];
    float x0 = b.x * inv, x1 = b.y * inv, x2 = b.z * inv, x3 = b.w * inv;
    __nv_bfloat16 h0 = __float2bfloat16(x0), h1 = __float2bfloat16(x1);
    __nv_bfloat16 h2 = __float2bfloat16(x2), h3 = __float2bfloat16(x3);
    __nv_bfloat16 l0 = __float2bfloat16(x0 - __bfloat162float(h0));
    __nv_bfloat16 l1 = __float2bfloat16(x1 - __bfloat162float(h1));
    __nv_bfloat16 l2 = __float2bfloat16(x2 - __bfloat162float(h2));
    __nv_bfloat16 l3 = __float2bfloat16(x3 - __bfloat162float(h3));
    __nv_bfloat162* hp = (__nv_bfloat162*)(ph + (size_t)k * Dd + tid * 4);
    __nv_bfloat162* lp = (__nv_bfloat162*)(pl + (size_t)k * Dd + tid * 4);
    hp[0] = __halves2bfloat162(h0, h1);
    hp[1] = __halves2bfloat162(h2, h3);
    lp[0] = __halves2bfloat162(l0, l1);
    lp[1] = __halves2bfloat162(l2, l3);
}

// ============================ launcher =======================================
extern "C" void kernel_launch(void* const* d_in, const int* in_sizes, int n_in,
                              void* d_out, int out_size)
{
    const float* cls   = (const float*)d_in[0];
    const float* proto = (const float*)d_in[1];
    if (n_in >= 2 && in_sizes[0] < in_sizes[1]) {
        const float* t = cls; cls = proto; proto = t;
    }

    __nv_bfloat16 *cls_h, *cls_l, *p_h, *p_l, *r_h, *r_l;
    float *logits, *parts;
    cudaGetSymbolAddress((void**)&cls_h,  g_cls_h);
    cudaGetSymbolAddress((void**)&cls_l,  g_cls_l);
    cudaGetSymbolAddress((void**)&p_h,    g_p_h);
    cudaGetSymbolAddress((void**)&p_l,    g_p_l);
    cudaGetSymbolAddress((void**)&r_h,    g_r_h);
    cudaGetSymbolAddress((void**)&r_l,    g_r_l);
    cudaGetSymbolAddress((void**)&logits, g_logits);
    cudaGetSymbolAddress((void**)&parts,  g_parts);

    cudaFuncSetAttribute(gemm_nt, cudaFuncAttributeMaxDynamicSharedMemorySize, SMEM_NT);
    cudaFuncSetAttribute(gemm_tt, cudaFuncAttributeMaxDynamicSharedMemorySize, SMEM_TT);
    cudaFuncSetAttribute(gemm_nn, cudaFuncAttributeMaxDynamicSharedMemorySize, SMEM_NN);

    float* r_out = (float*)d_out;                          // [Bq, Kp]
    float* z_out = (float*)d_out + (size_t)Bq * Kp;        // [Bq, Dd]

    split_f32<<<(Bq * Dd) / 1024, 256>>>(cls, cls_h, cls_l, Bq * Dd);
    split_f32<<<(Kp * Dd) / 1024, 256>>>(proto, p_h, p_l, Kp * Dd);

    dim3 g1(Kp / 128, Bq / 128);         // (4, 64)
    dim3 g2(Dd / 128, Kp / 128, SEG);    // (8, 4, 8)
    dim3 g3(Dd / 128, Bq / 128);         // (8, 64)

    for (int s = 0; s < STAGES; ++s) {
        gemm_nt<<<g1, 256, SMEM_NT>>>(cls_h, cls_l, Dd, p_h, p_l, Dd,
                                      Dd, logits, Kp);
        softmax_warp<<<Bq / 8, 256>>>(logits, r_h, r_l, nullptr);
        gemm_tt<<<g2, 256, SMEM_TT>>>(r_h, r_l, Kp, cls_h, cls_l, Dd,
                                      Bq / SEG, parts, Dd, (size_t)Kp * Dd);
        reduce_norm<<<Kp, 256>>>(parts, p_h, p_l);
    }

    gemm_nt<<<g1, 256, SMEM_NT>>>(cls_h, cls_l, Dd, p_h, p_l, Dd,
                                  Dd, logits, Kp);
    softmax_warp<<<Bq / 8, 256>>>(logits, r_h, r_l, r_out);
    gemm_nn<<<g3, 256, SMEM_NN>>>(r_h, Kp, p_h, Dd,
                                  Kp, z_out, Dd, cls);
}

// round 14
// speedup vs baseline: 1.0890x; 1.0343x over previous
#include <cuda_runtime.h>
#include <cuda_bf16.h>
#include <cstdint>
#include <math.h>

#define Bq 8192
#define Dd 1024
#define Kp 512
#define SEG 8
#define STAGES 5

// ============================ device globals (no allocs allowed) ============
__device__ __align__(16) __nv_bfloat16 g_cls_h[(size_t)Bq * Dd];
__device__ __align__(16) __nv_bfloat16 g_cls_l[(size_t)Bq * Dd];
__device__ __align__(16) __nv_bfloat16 g_p_h[(size_t)Kp * Dd];
__device__ __align__(16) __nv_bfloat16 g_p_l[(size_t)Kp * Dd];
__device__ __align__(16) __nv_bfloat16 g_r_h[(size_t)Bq * Kp];
__device__ __align__(16) __nv_bfloat16 g_r_l[(size_t)Bq * Kp];
__device__ __align__(16) float g_logits[(size_t)Bq * Kp];
__device__ __align__(16) float g_parts[(size_t)SEG * Kp * Dd];

// ============================ PTX helpers (base sm_103-safe) =================
__device__ __forceinline__ uint32_t smem_u32(const void* p) {
    uint32_t a;
    asm("{ .reg .u64 t; cvta.to.shared.u64 t, %1; cvt.u32.u64 %0, t; }" : "=r"(a) : "l"(p));
    return a;
}
#define CP_ASYNC16(sa, gp) \
    asm volatile("cp.async.cg.shared.global [%0], [%1], 16;" :: "r"(sa), "l"(gp))
#define CP_COMMIT() asm volatile("cp.async.commit_group;")
#define CP_WAIT1()  asm volatile("cp.async.wait_group 1;")
#define LDSM_X4(r0, r1, r2, r3, addr) \
    asm volatile("ldmatrix.sync.aligned.m8n8.x4.shared.b16 {%0,%1,%2,%3}, [%4];" \
        : "=r"(r0), "=r"(r1), "=r"(r2), "=r"(r3) : "r"(addr))
#define LDSM_X4T(r0, r1, r2, r3, addr) \
    asm volatile("ldmatrix.sync.aligned.m8n8.x4.trans.shared.b16 {%0,%1,%2,%3}, [%4];" \
        : "=r"(r0), "=r"(r1), "=r"(r2), "=r"(r3) : "r"(addr))
#define MMA16816(d, a, b0v, b1v) \
    asm volatile("mma.sync.aligned.m16n8k16.row.col.f32.bf16.bf16.f32 " \
        "{%0,%1,%2,%3}, {%4,%5,%6,%7}, {%8,%9}, {%0,%1,%2,%3};" \
        : "+f"((d)[0]), "+f"((d)[1]), "+f"((d)[2]), "+f"((d)[3]) \
        : "r"((a)[0]), "r"((a)[1]), "r"((a)[2]), "r"((a)[3]), "r"(b0v), "r"(b1v))

// Tiles: CTA 128x128, 8 warps (2x4), warp 64x32, 4x4 of m16n8, KC=32, 3 stages.
#define KC 32
#define SROW 40
#define TROW 136
#define NT_STG (128 * SROW * 2)        // 10240 B
#define TT_STG (KC * TROW * 2)         // 8704 B
#define SMEM_NT (6 * NT_STG)           // 61440
#define SMEM_TT (6 * TT_STG)           // 52224
#define SMEM_NN (3 * NT_STG + 3 * TT_STG)  // 56832

// ---------------- shared epilogue ----------------
__device__ __forceinline__ void epilogue(float acc[4][4][4], float* C, int ldc,
                                         int bm, int bn, int wm, int wn, int lane,
                                         const float* addsrc)
{
#pragma unroll
    for (int mt = 0; mt < 4; ++mt) {
        const int r0 = bm + wm * 64 + mt * 16 + (lane >> 2);
#pragma unroll
        for (int nt = 0; nt < 4; ++nt) {
            const int col = bn + wn * 32 + nt * 8 + (lane & 3) * 2;
            float2 v0 = make_float2(acc[mt][nt][0], acc[mt][nt][1]);
            float2 v1 = make_float2(acc[mt][nt][2], acc[mt][nt][3]);
            if (addsrc) {
                const float2 a0 = *(const float2*)(addsrc + (size_t)r0 * ldc + col);
                const float2 a1 = *(const float2*)(addsrc + (size_t)(r0 + 8) * ldc + col);
                v0.x += a0.x; v0.y += a0.y;
                v1.x += a1.x; v1.y += a1.y;
            }
            *(float2*)(C + (size_t)r0 * ldc + col) = v0;
            *(float2*)(C + (size_t)(r0 + 8) * ldc + col) = v1;
        }
    }
}

// ============================ GEMM NT: logits = cls @ p^T (3-term) ===========
__global__ void __launch_bounds__(256, 2)
gemm_nt(const __nv_bfloat16* __restrict__ Ah, const __nv_bfloat16* __restrict__ Al, int lda,
        const __nv_bfloat16* __restrict__ Bh, const __nv_bfloat16* __restrict__ Bl, int ldb,
        int Ksrc, float* __restrict__ C, int ldc)
{
    extern __shared__ char smem[];
    const uint32_t sAb = smem_u32(smem);
    const uint32_t sBb = sAb + 3 * NT_STG;
    const int tid = threadIdx.x, lane = tid & 31, wid = tid >> 5;
    const int wm = wid >> 2, wn = wid & 3;
    const int bm = blockIdx.y * 128, bn = blockIdx.x * 128;

    float acc[4][4][4] = {};
    const int cpb = Ksrc / KC, nch = 3 * cpb;
    const int lrow = tid >> 2, lcb = (tid & 3) * 16;

    auto issue = [&](int c) {
        const int stg = c % 3;
        const int t = c / cpb;
        const size_t kk = (size_t)(c - t * cpb) * KC;
        const __nv_bfloat16* As = (t == 1) ? Al : Ah;
        const __nv_bfloat16* Bs = (t == 2) ? Bl : Bh;
        const uint32_t sa = sAb + stg * NT_STG, sb = sBb + stg * NT_STG;
#pragma unroll
        for (int it = 0; it < 2; ++it) {
            int row = lrow + it * 64;
            CP_ASYNC16(sa + row * 80 + lcb, As + (size_t)(bm + row) * lda + kk + lcb / 2);
            CP_ASYNC16(sb + row * 80 + lcb, Bs + (size_t)(bn + row) * ldb + kk + lcb / 2);
        }
        CP_COMMIT();
    };

    issue(0); issue(1);
    for (int c = 0; c < nch; ++c) {
        CP_WAIT1();
        __syncthreads();
        const int buf = c % 3;
        const uint32_t sa = sAb + buf * NT_STG, sb = sBb + buf * NT_STG;
#pragma unroll
        for (int kg = 0; kg < 2; ++kg) {
            const int kb = kg * 32;
            uint32_t a[4][4], bf[2][4];
#pragma unroll
            for (int mt = 0; mt < 4; ++mt) {
                uint32_t ad = sa + (uint32_t)(wm * 64 + mt * 16 + (lane & 15)) * 80
                            + kb + ((lane >> 4) << 4);
                LDSM_X4(a[mt][0], a[mt][1], a[mt][2], a[mt][3], ad);
            }
#pragma unroll
            for (int nh = 0; nh < 2; ++nh) {
                uint32_t bd = sb + (uint32_t)(wn * 32 + nh * 16 + ((lane >> 3) & 1) * 8 + (lane & 7)) * 80
                            + kb + ((lane >> 4) << 4);
                LDSM_X4(bf[nh][0], bf[nh][1], bf[nh][2], bf[nh][3], bd);
            }
#pragma unroll
            for (int nt = 0; nt < 4; ++nt) {
                const int nh = nt >> 1, lo = nt & 1;
                const uint32_t b0 = bf[nh][lo], b1 = bf[nh][lo + 2];
#pragma unroll
                for (int mt = 0; mt < 4; ++mt)
                    MMA16816(acc[mt][nt], a[mt], b0, b1);
            }
        }
        if (c + 2 < nch) issue(c + 2);
    }
    epilogue(acc, C, ldc, bm, bn, wm, wn, lane, nullptr);
}

// ============================ GEMM TT: parts[seg] = r^T @ cls (3-term) =======
__global__ void __launch_bounds__(256, 2)
gemm_tt(const __nv_bfloat16* __restrict__ Ah, const __nv_bfloat16* __restrict__ Al, int lda,
        const __nv_bfloat16* __restrict__ Bh, const __nv_bfloat16* __restrict__ Bl, int ldb,
        int Kslab, float* __restrict__ C, int ldc, size_t zstride)
{
    extern __shared__ char smem[];
    const uint32_t sRb = smem_u32(smem);
    const uint32_t sCb = sRb + 3 * TT_STG;
    const int tid = threadIdx.x, lane = tid & 31, wid = tid >> 5;
    const int wm = wid >> 2, wn = wid & 3;
    const int bm = blockIdx.y * 128, bn = blockIdx.x * 128;
    const int b0seg = blockIdx.z * Kslab;
    C += (size_t)blockIdx.z * zstride;

    float acc[4][4][4] = {};
    const int cpb = Kslab / KC, nch = 3 * cpb;
    const int lrow = tid >> 3, lc16 = (tid & 7) * 16;

    auto issue = [&](int c) {
        const int stg = c % 3;
        const int t = c / cpb;
        const int kk = (c - t * cpb) * KC;
        const __nv_bfloat16* As = (t == 1) ? Al : Ah;
        const __nv_bfloat16* Bs = (t == 2) ? Bl : Bh;
        const uint32_t sr = sRb + stg * TT_STG, sc = sCb + stg * TT_STG;
        const size_t gb = (size_t)(b0seg + kk + lrow);
        CP_ASYNC16(sr + lrow * 272 + lc16 * 2,      As + gb * lda + bm + lc16);
        CP_ASYNC16(sr + lrow * 272 + lc16 * 2 + 16, As + gb * lda + bm + lc16 + 8);
        CP_ASYNC16(sc + lrow * 272 + lc16 * 2,      Bs + gb * ldb + bn + lc16);
        CP_ASYNC16(sc + lrow * 272 + lc16 * 2 + 16, Bs + gb * ldb + bn + lc16 + 8);
        CP_COMMIT();
    };

    issue(0); issue(1);
    for (int c = 0; c < nch; ++c) {
        CP_WAIT1();
        __syncthreads();
        const int buf = c % 3;
        const uint32_t sr = sRb + buf * TT_STG, sc = sCb + buf * TT_STG;
#pragma unroll
        for (int kg = 0; kg < 2; ++kg) {
            uint32_t a[4][4], bf[2][4];
#pragma unroll
            for (int mt = 0; mt < 4; ++mt) {
                uint32_t ad = sr + (uint32_t)(kg * 16 + ((lane >> 4) << 3) + (lane & 7)) * 272
                            + (uint32_t)(wm * 64 + mt * 16 + ((lane >> 3) & 1) * 8) * 2;
                LDSM_X4T(a[mt][0], a[mt][1], a[mt][2], a[mt][3], ad);
            }
#pragma unroll
            for (int nh = 0; nh < 2; ++nh) {
                uint32_t bd = sc + (uint32_t)(kg * 16 + ((lane >> 3) & 1) * 8 + (lane & 7)) * 272
                            + (uint32_t)(wn * 32 + nh * 16 + ((lane >> 4) << 3)) * 2;
                LDSM_X4T(bf[nh][0], bf[nh][1], bf[nh][2], bf[nh][3], bd);
            }
#pragma unroll
            for (int nt = 0; nt < 4; ++nt) {
                const int nh = nt >> 1, w = nt & 1;
                const uint32_t b0 = bf[nh][w * 2], b1 = bf[nh][w * 2 + 1];
#pragma unroll
                for (int mt = 0; mt < 4; ++mt)
                    MMA16816(acc[mt][nt], a[mt], b0, b1);
            }
        }
        if (c + 2 < nch) issue(c + 2);
    }
    epilogue(acc, C, ldc, bm, bn, wm, wn, lane, nullptr);
}

// ============================ GEMM NN (1-term): z = r_h @ p_h + cls ==========
__global__ void __launch_bounds__(256, 2)
gemm_nn(const __nv_bfloat16* __restrict__ Ah, int lda,
        const __nv_bfloat16* __restrict__ Bh, int ldb,
        int Ksrc, float* __restrict__ C, int ldc, const float* __restrict__ addsrc)
{
    extern __shared__ char smem[];
    const uint32_t sAb = smem_u32(smem);
    const uint32_t sBb = sAb + 3 * NT_STG;
    const int tid = threadIdx.x, lane = tid & 31, wid = tid >> 5;
    const int wm = wid >> 2, wn = wid & 3;
    const int bm = blockIdx.y * 128, bn = blockIdx.x * 128;

    float acc[4][4][4] = {};
    const int nch = Ksrc / KC;
    const int lrow = tid >> 2, lcb = (tid & 3) * 16;
    const int trow = tid >> 3, tc16 = (tid & 7) * 16;

    auto issue = [&](int c) {
        const int stg = c % 3;
        const int kk = c * KC;
        const uint32_t sa = sAb + stg * NT_STG, sb = sBb + stg * TT_STG;
#pragma unroll
        for (int it = 0; it < 2; ++it) {
            int row = lrow + it * 64;
            CP_ASYNC16(sa + row * 80 + lcb, Ah + (size_t)(bm + row) * lda + kk + lcb / 2);
        }
        CP_ASYNC16(sb + trow * 272 + tc16 * 2,      Bh + (size_t)(kk + trow) * ldb + bn + tc16);
        CP_ASYNC16(sb + trow * 272 + tc16 * 2 + 16, Bh + (size_t)(kk + trow) * ldb + bn + tc16 + 8);
        CP_COMMIT();
    };

    issue(0); issue(1);
    for (int c = 0; c < nch; ++c) {
        CP_WAIT1();
        __syncthreads();
        const int buf = c % 3;
        const uint32_t sa = sAb + buf * NT_STG, sb = sBb + buf * TT_STG;
#pragma unroll
        for (int kg = 0; kg < 2; ++kg) {
            const int kb = kg * 32;
            uint32_t a[4][4], bf[2][4];
#pragma unroll
            for (int mt = 0; mt < 4; ++mt) {
                uint32_t ad = sa + (uint32_t)(wm * 64 + mt * 16 + (lane & 15)) * 80
                            + kb + ((lane >> 4) << 4);
                LDSM_X4(a[mt][0], a[mt][1], a[mt][2], a[mt][3], ad);
            }
#pragma unroll
            for (int nh = 0; nh < 2; ++nh) {
                uint32_t bd = sb + (uint32_t)(kg * 16 + ((lane >> 3) & 1) * 8 + (lane & 7)) * 272
                            + (uint32_t)(wn * 32 + nh * 16 + ((lane >> 4) << 3)) * 2;
                LDSM_X4T(bf[nh][0], bf[nh][1], bf[nh][2], bf[nh][3], bd);
            }
#pragma unroll
            for (int nt = 0; nt < 4; ++nt) {
                const int nh = nt >> 1, w = nt & 1;
                const uint32_t b0 = bf[nh][w * 2], b1 = bf[nh][w * 2 + 1];
#pragma unroll
                for (int mt = 0; mt < 4; ++mt)
                    MMA16816(acc[mt][nt], a[mt], b0, b1);
            }
        }
        if (c + 2 < nch) issue(c + 2);
    }
    epilogue(acc, C, ldc, bm, bn, wm, wn, lane, addsrc);
}

// ============================ split fp32 -> bf16 hi/lo (fused both inputs) ===
__global__ void __launch_bounds__(256)
split_both(const float* __restrict__ x1, __nv_bfloat16* __restrict__ h1,
           __nv_bfloat16* __restrict__ l1, int n1,
           const float* __restrict__ x2, __nv_bfloat16* __restrict__ h2,
           __nv_bfloat16* __restrict__ l2, int n2)
{
    const int nb1 = n1 / 1024;   // blocks for tensor 1
    const float* x; __nv_bfloat16 *h, *l;
    int i;
    if ((int)blockIdx.x < nb1) {
        x = x1; h = h1; l = l1;
        i = (blockIdx.x * 256 + threadIdx.x) * 4;
        if (i >= n1) return;
    } else {
        x = x2; h = h2; l = l2;
        i = ((blockIdx.x - nb1) * 256 + threadIdx.x) * 4;
        if (i >= n2) return;
    }
    float4 v = *(const float4*)(x + i);
    __nv_bfloat16 h0 = __float2bfloat16(v.x), h1v = __float2bfloat16(v.y);
    __nv_bfloat16 h2v = __float2bfloat16(v.z), h3 = __float2bfloat16(v.w);
    __nv_bfloat16 l0 = __float2bfloat16(v.x - __bfloat162float(h0));
    __nv_bfloat16 l1v = __float2bfloat16(v.y - __bfloat162float(h1v));
    __nv_bfloat16 l2v = __float2bfloat16(v.z - __bfloat162float(h2v));
    __nv_bfloat16 l3 = __float2bfloat16(v.w - __bfloat162float(h3));
    ((__nv_bfloat162*)(h + i))[0] = __halves2bfloat162(h0, h1v);
    ((__nv_bfloat162*)(h + i))[1] = __halves2bfloat162(h2v, h3);
    ((__nv_bfloat162*)(l + i))[0] = __halves2bfloat162(l0, l1v);
    ((__nv_bfloat162*)(l + i))[1] = __halves2bfloat162(l2v, l3);
}

// ============================ softmax: one warp per 512-col row ==============
// Each lane owns 16 columns: 4x float4 at column (lane + j*32)*4, j=0..3.
// When rf != nullptr (final pass), r_l is dead downstream -> skip its writes.
__global__ void __launch_bounds__(256)
softmax_warp(const float* __restrict__ L, __nv_bfloat16* __restrict__ rh,
             __nv_bfloat16* __restrict__ rl, float* __restrict__ rf)
{
    const int row = blockIdx.x * 8 + (threadIdx.x >> 5);
    const int lane = threadIdx.x & 31;
    const float4* Lr = (const float4*)(L + (size_t)row * Kp);

    float4 v[4];
#pragma unroll
    for (int j = 0; j < 4; ++j) v[j] = Lr[lane + j * 32];

    float m = -1e30f;
#pragma unroll
    for (int j = 0; j < 4; ++j)
        m = fmaxf(m, fmaxf(fmaxf(v[j].x, v[j].y), fmaxf(v[j].z, v[j].w)));
#pragma unroll
    for (int o = 16; o; o >>= 1) m = fmaxf(m, __shfl_xor_sync(0xffffffffu, m, o));

    float4 e[4];
    float s = 0.f;
#pragma unroll
    for (int j = 0; j < 4; ++j) {
        e[j].x = __expf(v[j].x - m); e[j].y = __expf(v[j].y - m);
        e[j].z = __expf(v[j].z - m); e[j].w = __expf(v[j].w - m);
        s += (e[j].x + e[j].y) + (e[j].z + e[j].w);
    }
#pragma unroll
    for (int o = 16; o; o >>= 1) s += __shfl_xor_sync(0xffffffffu, s, o);

    const float inv = 1.0f / s;
    __nv_bfloat162* hp = (__nv_bfloat162*)(rh + (size_t)row * Kp);
    __nv_bfloat162* lp = (__nv_bfloat162*)(rl + (size_t)row * Kp);
    float4* rp = rf ? (float4*)(rf + (size_t)row * Kp) : nullptr;
#pragma unroll
    for (int j = 0; j < 4; ++j) {
        e[j].x *= inv; e[j].y *= inv; e[j].z *= inv; e[j].w *= inv;
        __nv_bfloat16 h0 = __float2bfloat16(e[j].x), h1 = __float2bfloat16(e[j].y);
        __nv_bfloat16 h2 = __float2bfloat16(e[j].z), h3 = __float2bfloat16(e[j].w);
        const int c2 = (lane + j * 32) * 2;
        hp[c2 + 0] = __halves2bfloat162(h0, h1);
        hp[c2 + 1] = __halves2bfloat162(h2, h3);
        if (rp) {
            rp[lane + j * 32] = e[j];
        } else {
            __nv_bfloat16 l0 = __float2bfloat16(e[j].x - __bfloat162float(h0));
            __nv_bfloat16 l1 = __float2bfloat16(e[j].y - __bfloat162float(h1));
            __nv_bfloat16 l2 = __float2bfloat16(e[j].z - __bfloat162float(h2));
            __nv_bfloat16 l3 = __float2bfloat16(e[j].w - __bfloat162float(h3));
            lp[c2 + 0] = __halves2bfloat162(l0, l1);
            lp[c2 + 1] = __halves2bfloat162(l2, l3);
        }
    }
}

// ============================ reduce split-K + L2 normalize (vectorized) =====
__global__ void __launch_bounds__(256)
reduce_norm(const float* __restrict__ parts, __nv_bfloat16* __restrict__ ph,
            __nv_bfloat16* __restrict__ pl)
{
    const int k = blockIdx.x;
    const int tid = threadIdx.x;
    __shared__ float4 buf[Dd / 4];
    __shared__ float wred[8];
    __shared__ float sden;

    float4 s = make_float4(0.f, 0.f, 0.f, 0.f);
#pragma unroll
    for (int g = 0; g < SEG; ++g) {
        const float4 v = *(const float4*)(parts + (size_t)g * Kp * Dd + (size_t)k * Dd + tid * 4);
        s.x += v.x; s.y += v.y; s.z += v.z; s.w += v.w;
    }
    buf[tid] = s;
    float sq = s.x * s.x + s.y * s.y + s.z * s.z + s.w * s.w;
#pragma unroll
    for (int o = 16; o; o >>= 1) sq += __shfl_xor_sync(0xffffffffu, sq, o);
    if ((tid & 31) == 0) wred[tid >> 5] = sq;
    __syncthreads();
    if (tid == 0) {
        float t = 0.f;
#pragma unroll
        for (int i = 0; i < 8; ++i) t += wred[i];
        sden = sqrtf(t) + 1e-6f;
    }
    __syncthreads();
    const float inv = 1.0f / sden;
    const float4 b = buf[tid];
    float x0 = b.x * inv, x1 = b.y * inv, x2 = b.z * inv, x3 = b.w * inv;
    __nv_bfloat16 h0 = __float2bfloat16(x0), h1 = __float2bfloat16(x1);
    __nv_bfloat16 h2 = __float2bfloat16(x2), h3 = __float2bfloat16(x3);
    __nv_bfloat16 l0 = __float2bfloat16(x0 - __bfloat162float(h0));
    __nv_bfloat16 l1 = __float2bfloat16(x1 - __bfloat162float(h1));
    __nv_bfloat16 l2 = __float2bfloat16(x2 - __bfloat162float(h2));
    __nv_bfloat16 l3 = __float2bfloat16(x3 - __bfloat162float(h3));
    __nv_bfloat162* hp = (__nv_bfloat162*)(ph + (size_t)k * Dd + tid * 4);
    __nv_bfloat162* lp = (__nv_bfloat162*)(pl + (size_t)k * Dd + tid * 4);
    hp[0] = __halves2bfloat162(h0, h1);
    hp[1] = __halves2bfloat162(h2, h3);
    lp[0] = __halves2bfloat162(l0, l1);
    lp[1] = __halves2bfloat162(l2, l3);
}

// ============================ launcher =======================================
extern "C" void kernel_launch(void* const* d_in, const int* in_sizes, int n_in,
                              void* d_out, int out_size)
{
    const float* cls   = (const float*)d_in[0];
    const float* proto = (const float*)d_in[1];
    if (n_in >= 2 && in_sizes[0] < in_sizes[1]) {
        const float* t = cls; cls = proto; proto = t;
    }

    __nv_bfloat16 *cls_h, *cls_l, *p_h, *p_l, *r_h, *r_l;
    float *logits, *parts;
    cudaGetSymbolAddress((void**)&cls_h,  g_cls_h);
    cudaGetSymbolAddress((void**)&cls_l,  g_cls_l);
    cudaGetSymbolAddress((void**)&p_h,    g_p_h);
    cudaGetSymbolAddress((void**)&p_l,    g_p_l);
    cudaGetSymbolAddress((void**)&r_h,    g_r_h);
    cudaGetSymbolAddress((void**)&r_l,    g_r_l);
    cudaGetSymbolAddress((void**)&logits, g_logits);
    cudaGetSymbolAddress((void**)&parts,  g_parts);

    cudaFuncSetAttribute(gemm_nt, cudaFuncAttributeMaxDynamicSharedMemorySize, SMEM_NT);
    cudaFuncSetAttribute(gemm_tt, cudaFuncAttributeMaxDynamicSharedMemorySize, SMEM_TT);
    cudaFuncSetAttribute(gemm_nn, cudaFuncAttributeMaxDynamicSharedMemorySize, SMEM_NN);

    float* r_out = (float*)d_out;                          // [Bq, Kp]
    float* z_out = (float*)d_out + (size_t)Bq * Kp;        // [Bq, Dd]

    split_both<<<(Bq * Dd + Kp * Dd) / 1024, 256>>>(cls, cls_h, cls_l, Bq * Dd,
                                                    proto, p_h, p_l, Kp * Dd);

    dim3 g1(Kp / 128, Bq / 128);         // (4, 64)
    dim3 g2(Dd / 128, Kp / 128, SEG);    // (8, 4, 8)
    dim3 g3(Dd / 128, Bq / 128);         // (8, 64)

    for (int s = 0; s < STAGES; ++s) {
        gemm_nt<<<g1, 256, SMEM_NT>>>(cls_h, cls_l, Dd, p_h, p_l, Dd,
                                      Dd, logits, Kp);
        softmax_warp<<<Bq / 8, 256>>>(logits, r_h, r_l, nullptr);
        gemm_tt<<<g2, 256, SMEM_TT>>>(r_h, r_l, Kp, cls_h, cls_l, Dd,
                                      Bq / SEG, parts, Dd, (size_t)Kp * Dd);
        reduce_norm<<<Kp, 256>>>(parts, p_h, p_l);
    }

    gemm_nt<<<g1, 256, SMEM_NT>>>(cls_h, cls_l, Dd, p_h, p_l, Dd,
                                  Dd, logits, Kp);
    softmax_warp<<<Bq / 8, 256>>>(logits, r_h, r_l, r_out);
    gemm_nn<<<g3, 256, SMEM_NN>>>(r_h, Kp, p_h, Dd,
                                  Kp, z_out, Dd, cls);
}

// round 16
// speedup vs baseline: 1.0903x; 1.0012x over previous
#include <cuda_runtime.h>
#include <cuda_bf16.h>
#include <cstdint>
#include <math.h>

#define Bq 8192
#define Dd 1024
#define Kp 512
#define SEG 8
#define STAGES 5

// ============================ device globals (no allocs allowed) ============
__device__ __align__(16) __nv_bfloat16 g_cls_h[(size_t)Bq * Dd];
__device__ __align__(16) __nv_bfloat16 g_cls_l[(size_t)Bq * Dd];
__device__ __align__(16) __nv_bfloat16 g_p_h[(size_t)Kp * Dd];
__device__ __align__(16) __nv_bfloat16 g_p_l[(size_t)Kp * Dd];
__device__ __align__(16) __nv_bfloat16 g_r_h[(size_t)Bq * Kp];
__device__ __align__(16) __nv_bfloat16 g_r_l[(size_t)Bq * Kp];
__device__ __align__(16) float g_logits[(size_t)Bq * Kp];
__device__ __align__(16) float g_parts[(size_t)SEG * Kp * Dd];

// ============================ PTX helpers (base sm_103-safe) =================
__device__ __forceinline__ uint32_t smem_u32(const void* p) {
    uint32_t a;
    asm("{ .reg .u64 t; cvta.to.shared.u64 t, %1; cvt.u32.u64 %0, t; }" : "=r"(a) : "l"(p));
    return a;
}
#define CP_ASYNC16(sa, gp) \
    asm volatile("cp.async.cg.shared.global [%0], [%1], 16;" :: "r"(sa), "l"(gp))
#define CP_COMMIT() asm volatile("cp.async.commit_group;")
#define CP_WAIT1()  asm volatile("cp.async.wait_group 1;")
#define LDSM_X4(r0, r1, r2, r3, addr) \
    asm volatile("ldmatrix.sync.aligned.m8n8.x4.shared.b16 {%0,%1,%2,%3}, [%4];" \
        : "=r"(r0), "=r"(r1), "=r"(r2), "=r"(r3) : "r"(addr))
#define LDSM_X4T(r0, r1, r2, r3, addr) \
    asm volatile("ldmatrix.sync.aligned.m8n8.x4.trans.shared.b16 {%0,%1,%2,%3}, [%4];" \
        : "=r"(r0), "=r"(r1), "=r"(r2), "=r"(r3) : "r"(addr))
#define MMA16816(d, a, b0v, b1v) \
    asm volatile("mma.sync.aligned.m16n8k16.row.col.f32.bf16.bf16.f32 " \
        "{%0,%1,%2,%3}, {%4,%5,%6,%7}, {%8,%9}, {%0,%1,%2,%3};" \
        : "+f"((d)[0]), "+f"((d)[1]), "+f"((d)[2]), "+f"((d)[3]) \
        : "r"((a)[0]), "r"((a)[1]), "r"((a)[2]), "r"((a)[3]), "r"(b0v), "r"(b1v))

// Tiles: CTA 128x128, 8 warps (2x4), warp 64x32, 4x4 of m16n8, KC=32, 3 stages.
#define KC 32
#define SROW 40
#define TROW 136
#define NT_STG (128 * SROW * 2)        // 10240 B
#define TT_STG (KC * TROW * 2)         // 8704 B
#define SMEM_NT (6 * NT_STG)           // 61440
#define SMEM_TT (6 * TT_STG)           // 52224
#define SMEM_NN (3 * NT_STG + 3 * TT_STG)  // 56832

// ---------------- shared epilogue ----------------
__device__ __forceinline__ void epilogue(float acc[4][4][4], float* C, int ldc,
                                         int bm, int bn, int wm, int wn, int lane,
                                         const float* addsrc)
{
#pragma unroll
    for (int mt = 0; mt < 4; ++mt) {
        const int r0 = bm + wm * 64 + mt * 16 + (lane >> 2);
#pragma unroll
        for (int nt = 0; nt < 4; ++nt) {
            const int col = bn + wn * 32 + nt * 8 + (lane & 3) * 2;
            float2 v0 = make_float2(acc[mt][nt][0], acc[mt][nt][1]);
            float2 v1 = make_float2(acc[mt][nt][2], acc[mt][nt][3]);
            if (addsrc) {
                const float2 a0 = *(const float2*)(addsrc + (size_t)r0 * ldc + col);
                const float2 a1 = *(const float2*)(addsrc + (size_t)(r0 + 8) * ldc + col);
                v0.x += a0.x; v0.y += a0.y;
                v1.x += a1.x; v1.y += a1.y;
            }
            *(float2*)(C + (size_t)r0 * ldc + col) = v0;
            *(float2*)(C + (size_t)(r0 + 8) * ldc + col) = v1;
        }
    }
}

// ============================ GEMM NT: logits = cls @ p^T (3-term) ===========
__global__ void __launch_bounds__(256, 2)
gemm_nt(const __nv_bfloat16* __restrict__ Ah, const __nv_bfloat16* __restrict__ Al, int lda,
        const __nv_bfloat16* __restrict__ Bh, const __nv_bfloat16* __restrict__ Bl, int ldb,
        int Ksrc, float* __restrict__ C, int ldc)
{
    extern __shared__ char smem[];
    const uint32_t sAb = smem_u32(smem);
    const uint32_t sBb = sAb + 3 * NT_STG;
    const int tid = threadIdx.x, lane = tid & 31, wid = tid >> 5;
    const int wm = wid >> 2, wn = wid & 3;
    const int bm = blockIdx.y * 128, bn = blockIdx.x * 128;

    float acc[4][4][4] = {};
    const int cpb = Ksrc / KC, nch = 3 * cpb;
    const int lrow = tid >> 2, lcb = (tid & 3) * 16;

    auto issue = [&](int c) {
        const int stg = c % 3;
        const int t = c / cpb;
        const size_t kk = (size_t)(c - t * cpb) * KC;
        const __nv_bfloat16* As = (t == 1) ? Al : Ah;
        const __nv_bfloat16* Bs = (t == 2) ? Bl : Bh;
        const uint32_t sa = sAb + stg * NT_STG, sb = sBb + stg * NT_STG;
#pragma unroll
        for (int it = 0; it < 2; ++it) {
            int row = lrow + it * 64;
            CP_ASYNC16(sa + row * 80 + lcb, As + (size_t)(bm + row) * lda + kk + lcb / 2);
            CP_ASYNC16(sb + row * 80 + lcb, Bs + (size_t)(bn + row) * ldb + kk + lcb / 2);
        }
        CP_COMMIT();
    };

    issue(0); issue(1);
    for (int c = 0; c < nch; ++c) {
        CP_WAIT1();
        __syncthreads();
        const int buf = c % 3;
        const uint32_t sa = sAb + buf * NT_STG, sb = sBb + buf * NT_STG;
#pragma unroll
        for (int kg = 0; kg < 2; ++kg) {
            const int kb = kg * 32;
            uint32_t a[4][4], bf[2][4];
#pragma unroll
            for (int mt = 0; mt < 4; ++mt) {
                uint32_t ad = sa + (uint32_t)(wm * 64 + mt * 16 + (lane & 15)) * 80
                            + kb + ((lane >> 4) << 4);
                LDSM_X4(a[mt][0], a[mt][1], a[mt][2], a[mt][3], ad);
            }
#pragma unroll
            for (int nh = 0; nh < 2; ++nh) {
                uint32_t bd = sb + (uint32_t)(wn * 32 + nh * 16 + ((lane >> 3) & 1) * 8 + (lane & 7)) * 80
                            + kb + ((lane >> 4) << 4);
                LDSM_X4(bf[nh][0], bf[nh][1], bf[nh][2], bf[nh][3], bd);
            }
#pragma unroll
            for (int nt = 0; nt < 4; ++nt) {
                const int nh = nt >> 1, lo = nt & 1;
                const uint32_t b0 = bf[nh][lo], b1 = bf[nh][lo + 2];
#pragma unroll
                for (int mt = 0; mt < 4; ++mt)
                    MMA16816(acc[mt][nt], a[mt], b0, b1);
            }
        }
        if (c + 2 < nch) issue(c + 2);
    }
    epilogue(acc, C, ldc, bm, bn, wm, wn, lane, nullptr);
}

// ============================ GEMM TT: parts[seg] = r^T @ cls (3-term) =======
__global__ void __launch_bounds__(256, 2)
gemm_tt(const __nv_bfloat16* __restrict__ Ah, const __nv_bfloat16* __restrict__ Al, int lda,
        const __nv_bfloat16* __restrict__ Bh, const __nv_bfloat16* __restrict__ Bl, int ldb,
        int Kslab, float* __restrict__ C, int ldc, size_t zstride)
{
    extern __shared__ char smem[];
    const uint32_t sRb = smem_u32(smem);
    const uint32_t sCb = sRb + 3 * TT_STG;
    const int tid = threadIdx.x, lane = tid & 31, wid = tid >> 5;
    const int wm = wid >> 2, wn = wid & 3;
    const int bm = blockIdx.y * 128, bn = blockIdx.x * 128;
    const int b0seg = blockIdx.z * Kslab;
    C += (size_t)blockIdx.z * zstride;

    float acc[4][4][4] = {};
    const int cpb = Kslab / KC, nch = 3 * cpb;
    const int lrow = tid >> 3, lc16 = (tid & 7) * 16;

    auto issue = [&](int c) {
        const int stg = c % 3;
        const int t = c / cpb;
        const int kk = (c - t * cpb) * KC;
        const __nv_bfloat16* As = (t == 1) ? Al : Ah;
        const __nv_bfloat16* Bs = (t == 2) ? Bl : Bh;
        const uint32_t sr = sRb + stg * TT_STG, sc = sCb + stg * TT_STG;
        const size_t gb = (size_t)(b0seg + kk + lrow);
        CP_ASYNC16(sr + lrow * 272 + lc16 * 2,      As + gb * lda + bm + lc16);
        CP_ASYNC16(sr + lrow * 272 + lc16 * 2 + 16, As + gb * lda + bm + lc16 + 8);
        CP_ASYNC16(sc + lrow * 272 + lc16 * 2,      Bs + gb * ldb + bn + lc16);
        CP_ASYNC16(sc + lrow * 272 + lc16 * 2 + 16, Bs + gb * ldb + bn + lc16 + 8);
        CP_COMMIT();
    };

    issue(0); issue(1);
    for (int c = 0; c < nch; ++c) {
        CP_WAIT1();
        __syncthreads();
        const int buf = c % 3;
        const uint32_t sr = sRb + buf * TT_STG, sc = sCb + buf * TT_STG;
#pragma unroll
        for (int kg = 0; kg < 2; ++kg) {
            uint32_t a[4][4], bf[2][4];
#pragma unroll
            for (int mt = 0; mt < 4; ++mt) {
                uint32_t ad = sr + (uint32_t)(kg * 16 + ((lane >> 4) << 3) + (lane & 7)) * 272
                            + (uint32_t)(wm * 64 + mt * 16 + ((lane >> 3) & 1) * 8) * 2;
                LDSM_X4T(a[mt][0], a[mt][1], a[mt][2], a[mt][3], ad);
            }
#pragma unroll
            for (int nh = 0; nh < 2; ++nh) {
                uint32_t bd = sc + (uint32_t)(kg * 16 + ((lane >> 3) & 1) * 8 + (lane & 7)) * 272
                            + (uint32_t)(wn * 32 + nh * 16 + ((lane >> 4) << 3)) * 2;
                LDSM_X4T(bf[nh][0], bf[nh][1], bf[nh][2], bf[nh][3], bd);
            }
#pragma unroll
            for (int nt = 0; nt < 4; ++nt) {
                const int nh = nt >> 1, w = nt & 1;
                const uint32_t b0 = bf[nh][w * 2], b1 = bf[nh][w * 2 + 1];
#pragma unroll
                for (int mt = 0; mt < 4; ++mt)
                    MMA16816(acc[mt][nt], a[mt], b0, b1);
            }
        }
        if (c + 2 < nch) issue(c + 2);
    }
    epilogue(acc, C, ldc, bm, bn, wm, wn, lane, nullptr);
}

// ============================ GEMM NN (1-term): z = r_h @ p_h + cls ==========
__global__ void __launch_bounds__(256, 2)
gemm_nn(const __nv_bfloat16* __restrict__ Ah, int lda,
        const __nv_bfloat16* __restrict__ Bh, int ldb,
        int Ksrc, float* __restrict__ C, int ldc, const float* __restrict__ addsrc)
{
    extern __shared__ char smem[];
    const uint32_t sAb = smem_u32(smem);
    const uint32_t sBb = sAb + 3 * NT_STG;
    const int tid = threadIdx.x, lane = tid & 31, wid = tid >> 5;
    const int wm = wid >> 2, wn = wid & 3;
    const int bm = blockIdx.y * 128, bn = blockIdx.x * 128;

    float acc[4][4][4] = {};
    const int nch = Ksrc / KC;
    const int lrow = tid >> 2, lcb = (tid & 3) * 16;
    const int trow = tid >> 3, tc16 = (tid & 7) * 16;

    auto issue = [&](int c) {
        const int stg = c % 3;
        const int kk = c * KC;
        const uint32_t sa = sAb + stg * NT_STG, sb = sBb + stg * TT_STG;
#pragma unroll
        for (int it = 0; it < 2; ++it) {
            int row = lrow + it * 64;
            CP_ASYNC16(sa + row * 80 + lcb, Ah + (size_t)(bm + row) * lda + kk + lcb / 2);
        }
        CP_ASYNC16(sb + trow * 272 + tc16 * 2,      Bh + (size_t)(kk + trow) * ldb + bn + tc16);
        CP_ASYNC16(sb + trow * 272 + tc16 * 2 + 16, Bh + (size_t)(kk + trow) * ldb + bn + tc16 + 8);
        CP_COMMIT();
    };

    issue(0); issue(1);
    for (int c = 0; c < nch; ++c) {
        CP_WAIT1();
        __syncthreads();
        const int buf = c % 3;
        const uint32_t sa = sAb + buf * NT_STG, sb = sBb + buf * TT_STG;
#pragma unroll
        for (int kg = 0; kg < 2; ++kg) {
            const int kb = kg * 32;
            uint32_t a[4][4], bf[2][4];
#pragma unroll
            for (int mt = 0; mt < 4; ++mt) {
                uint32_t ad = sa + (uint32_t)(wm * 64 + mt * 16 + (lane & 15)) * 80
                            + kb + ((lane >> 4) << 4);
                LDSM_X4(a[mt][0], a[mt][1], a[mt][2], a[mt][3], ad);
            }
#pragma unroll
            for (int nh = 0; nh < 2; ++nh) {
                uint32_t bd = sb + (uint32_t)(kg * 16 + ((lane >> 3) & 1) * 8 + (lane & 7)) * 272
                            + (uint32_t)(wn * 32 + nh * 16 + ((lane >> 4) << 3)) * 2;
                LDSM_X4T(bf[nh][0], bf[nh][1], bf[nh][2], bf[nh][3], bd);
            }
#pragma unroll
            for (int nt = 0; nt < 4; ++nt) {
                const int nh = nt >> 1, w = nt & 1;
                const uint32_t b0 = bf[nh][w * 2], b1 = bf[nh][w * 2 + 1];
#pragma unroll
                for (int mt = 0; mt < 4; ++mt)
                    MMA16816(acc[mt][nt], a[mt], b0, b1);
            }
        }
        if (c + 2 < nch) issue(c + 2);
    }
    epilogue(acc, C, ldc, bm, bn, wm, wn, lane, addsrc);
}

// ============================ split fp32 -> bf16 hi/lo (fused both inputs) ===
__global__ void __launch_bounds__(256)
split_both(const float* __restrict__ x1, __nv_bfloat16* __restrict__ h1,
           __nv_bfloat16* __restrict__ l1, int n1,
           const float* __restrict__ x2, __nv_bfloat16* __restrict__ h2,
           __nv_bfloat16* __restrict__ l2, int n2)
{
    const int nb1 = n1 / 1024;
    const float* x; __nv_bfloat16 *h, *l;
    int i;
    if ((int)blockIdx.x < nb1) {
        x = x1; h = h1; l = l1;
        i = (blockIdx.x * 256 + threadIdx.x) * 4;
        if (i >= n1) return;
    } else {
        x = x2; h = h2; l = l2;
        i = ((blockIdx.x - nb1) * 256 + threadIdx.x) * 4;
        if (i >= n2) return;
    }
    float4 v = *(const float4*)(x + i);
    __nv_bfloat16 h0 = __float2bfloat16(v.x), h1v = __float2bfloat16(v.y);
    __nv_bfloat16 h2v = __float2bfloat16(v.z), h3 = __float2bfloat16(v.w);
    __nv_bfloat16 l0 = __float2bfloat16(v.x - __bfloat162float(h0));
    __nv_bfloat16 l1v = __float2bfloat16(v.y - __bfloat162float(h1v));
    __nv_bfloat16 l2v = __float2bfloat16(v.z - __bfloat162float(h2v));
    __nv_bfloat16 l3 = __float2bfloat16(v.w - __bfloat162float(h3));
    ((__nv_bfloat162*)(h + i))[0] = __halves2bfloat162(h0, h1v);
    ((__nv_bfloat162*)(h + i))[1] = __halves2bfloat162(h2v, h3);
    ((__nv_bfloat162*)(l + i))[0] = __halves2bfloat162(l0, l1v);
    ((__nv_bfloat162*)(l + i))[1] = __halves2bfloat162(l2v, l3);
}

// ============================ softmax: one warp per 512-col row ==============
// Each lane owns 16 columns: 4x float4 at column (lane + j*32)*4, j=0..3.
// When rf != nullptr (final pass), r_l is dead downstream -> skip its writes.
__global__ void __launch_bounds__(256)
softmax_warp(const float* __restrict__ L, __nv_bfloat16* __restrict__ rh,
             __nv_bfloat16* __restrict__ rl, float* __restrict__ rf)
{
    const int row = blockIdx.x * 8 + (threadIdx.x >> 5);
    const int lane = threadIdx.x & 31;
    const float4* Lr = (const float4*)(L + (size_t)row * Kp);

    float4 v[4];
#pragma unroll
    for (int j = 0; j < 4; ++j) v[j] = Lr[lane + j * 32];

    float m = -1e30f;
#pragma unroll
    for (int j = 0; j < 4; ++j)
        m = fmaxf(m, fmaxf(fmaxf(v[j].x, v[j].y), fmaxf(v[j].z, v[j].w)));
#pragma unroll
    for (int o = 16; o; o >>= 1) m = fmaxf(m, __shfl_xor_sync(0xffffffffu, m, o));

    float4 e[4];
    float s = 0.f;
#pragma unroll
    for (int j = 0; j < 4; ++j) {
        e[j].x = __expf(v[j].x - m); e[j].y = __expf(v[j].y - m);
        e[j].z = __expf(v[j].z - m); e[j].w = __expf(v[j].w - m);
        s += (e[j].x + e[j].y) + (e[j].z + e[j].w);
    }
#pragma unroll
    for (int o = 16; o; o >>= 1) s += __shfl_xor_sync(0xffffffffu, s, o);

    const float inv = 1.0f / s;
    __nv_bfloat162* hp = (__nv_bfloat162*)(rh + (size_t)row * Kp);
    __nv_bfloat162* lp = (__nv_bfloat162*)(rl + (size_t)row * Kp);
    float4* rp = rf ? (float4*)(rf + (size_t)row * Kp) : nullptr;
#pragma unroll
    for (int j = 0; j < 4; ++j) {
        e[j].x *= inv; e[j].y *= inv; e[j].z *= inv; e[j].w *= inv;
        __nv_bfloat16 h0 = __float2bfloat16(e[j].x), h1 = __float2bfloat16(e[j].y);
        __nv_bfloat16 h2 = __float2bfloat16(e[j].z), h3 = __float2bfloat16(e[j].w);
        const int c2 = (lane + j * 32) * 2;
        hp[c2 + 0] = __halves2bfloat162(h0, h1);
        hp[c2 + 1] = __halves2bfloat162(h2, h3);
        if (rp) {
            rp[lane + j * 32] = e[j];
        } else {
            __nv_bfloat16 l0 = __float2bfloat16(e[j].x - __bfloat162float(h0));
            __nv_bfloat16 l1 = __float2bfloat16(e[j].y - __bfloat162float(h1));
            __nv_bfloat16 l2 = __float2bfloat16(e[j].z - __bfloat162float(h2));
            __nv_bfloat16 l3 = __float2bfloat16(e[j].w - __bfloat162float(h3));
            lp[c2 + 0] = __halves2bfloat162(l0, l1);
            lp[c2 + 1] = __halves2bfloat162(l2, l3);
        }
    }
}

// ============================ reduce split-K + L2 normalize (vectorized) =====
__global__ void __launch_bounds__(256)
reduce_norm(const float* __restrict__ parts, __nv_bfloat16* __restrict__ ph,
            __nv_bfloat16* __restrict__ pl)
{
    const int k = blockIdx.x;
    const int tid = threadIdx.x;
    __shared__ float4 buf[Dd / 4];
    __shared__ float wred[8];
    __shared__ float sden;

    float4 s = make_float4(0.f, 0.f, 0.f, 0.f);
#pragma unroll
    for (int g = 0; g < SEG; ++g) {
        const float4 v = *(const float4*)(parts + (size_t)g * Kp * Dd + (size_t)k * Dd + tid * 4);
        s.x += v.x; s.y += v.y; s.z += v.z; s.w += v.w;
    }
    buf[tid] = s;
    float sq = s.x * s.x + s.y * s.y + s.z * s.z + s.w * s.w;
#pragma unroll
    for (int o = 16; o; o >>= 1) sq += __shfl_xor_sync(0xffffffffu, sq, o);
    if ((tid & 31) == 0) wred[tid >> 5] = sq;
    __syncthreads();
    if (tid == 0) {
        float t = 0.f;
#pragma unroll
        for (int i = 0; i < 8; ++i) t += wred[i];
        sden = sqrtf(t) + 1e-6f;
    }
    __syncthreads();
    const float inv = 1.0f / sden;
    const float4 b = buf[tid];
    float x0 = b.x * inv, x1 = b.y * inv, x2 = b.z * inv, x3 = b.w * inv;
    __nv_bfloat16 h0 = __float2bfloat16(x0), h1 = __float2bfloat16(x1);
    __nv_bfloat16 h2 = __float2bfloat16(x2), h3 = __float2bfloat16(x3);
    __nv_bfloat16 l0 = __float2bfloat16(x0 - __bfloat162float(h0));
    __nv_bfloat16 l1 = __float2bfloat16(x1 - __bfloat162float(h1));
    __nv_bfloat16 l2 = __float2bfloat16(x2 - __bfloat162float(h2));
    __nv_bfloat16 l3 = __float2bfloat16(x3 - __bfloat162float(h3));
    __nv_bfloat162* hp = (__nv_bfloat162*)(ph + (size_t)k * Dd + tid * 4);
    __nv_bfloat162* lp = (__nv_bfloat162*)(pl + (size_t)k * Dd + tid * 4);
    hp[0] = __halves2bfloat162(h0, h1);
    hp[1] = __halves2bfloat162(h2, h3);
    lp[0] = __halves2bfloat162(l0, l1);
    lp[1] = __halves2bfloat162(l2, l3);
}

// ============================ launcher =======================================
extern "C" void kernel_launch(void* const* d_in, const int* in_sizes, int n_in,
                              void* d_out, int out_size)
{
    const float* cls   = (const float*)d_in[0];
    const float* proto = (const float*)d_in[1];
    if (n_in >= 2 && in_sizes[0] < in_sizes[1]) {
        const float* t = cls; cls = proto; proto = t;
    }

    __nv_bfloat16 *cls_h, *cls_l, *p_h, *p_l, *r_h, *r_l;
    float *logits, *parts;
    cudaGetSymbolAddress((void**)&cls_h,  g_cls_h);
    cudaGetSymbolAddress((void**)&cls_l,  g_cls_l);
    cudaGetSymbolAddress((void**)&p_h,    g_p_h);
    cudaGetSymbolAddress((void**)&p_l,    g_p_l);
    cudaGetSymbolAddress((void**)&r_h,    g_r_h);
    cudaGetSymbolAddress((void**)&r_l,    g_r_l);
    cudaGetSymbolAddress((void**)&logits, g_logits);
    cudaGetSymbolAddress((void**)&parts,  g_parts);

    cudaFuncSetAttribute(gemm_nt, cudaFuncAttributeMaxDynamicSharedMemorySize, SMEM_NT);
    cudaFuncSetAttribute(gemm_tt, cudaFuncAttributeMaxDynamicSharedMemorySize, SMEM_TT);
    cudaFuncSetAttribute(gemm_nn, cudaFuncAttributeMaxDynamicSharedMemorySize, SMEM_NN);

    float* r_out = (float*)d_out;                          // [Bq, Kp]
    float* z_out = (float*)d_out + (size_t)Bq * Kp;        // [Bq, Dd]

    split_both<<<(Bq * Dd + Kp * Dd) / 1024, 256>>>(cls, cls_h, cls_l, Bq * Dd,
                                                    proto, p_h, p_l, Kp * Dd);

    dim3 g1(Kp / 128, Bq / 128);         // (4, 64)
    dim3 g2(Dd / 128, Kp / 128, SEG);    // (8, 4, 8)
    dim3 g3(Dd / 128, Bq / 128);         // (8, 64)

    for (int s = 0; s < STAGES; ++s) {
        gemm_nt<<<g1, 256, SMEM_NT>>>(cls_h, cls_l, Dd, p_h, p_l, Dd,
                                      Dd, logits, Kp);
        softmax_warp<<<Bq / 8, 256>>>(logits, r_h, r_l, nullptr);
        gemm_tt<<<g2, 256, SMEM_TT>>>(r_h, r_l, Kp, cls_h, cls_l, Dd,
                                      Bq / SEG, parts, Dd, (size_t)Kp * Dd);
        reduce_norm<<<Kp, 256>>>(parts, p_h, p_l);
    }

    gemm_nt<<<g1, 256, SMEM_NT>>>(cls_h, cls_l, Dd, p_h, p_l, Dd,
                                  Dd, logits, Kp);
    softmax_warp<<<Bq / 8, 256>>>(logits, r_h, r_l, r_out);
    gemm_nn<<<g3, 256, SMEM_NN>>>(r_h, Kp, p_h, Dd,
                                  Kp, z_out, Dd, cls);
}

// round 17
// speedup vs baseline: 1.1247x; 1.0316x over previous
#include <cuda_runtime.h>
#include <cuda_bf16.h>
#include <cstdint>
#include <math.h>

#define Bq 8192
#define Dd 1024
#define Kp 512
#define NSLAB 9     // uneven split-K: 4 slabs of 29 chunks + 5 of 28 (256 total)
#define STAGES 5

// ============================ device globals (no allocs allowed) ============
__device__ __align__(16) __nv_bfloat16 g_cls_h[(size_t)Bq * Dd];
__device__ __align__(16) __nv_bfloat16 g_cls_l[(size_t)Bq * Dd];
__device__ __align__(16) __nv_bfloat16 g_p_h[(size_t)Kp * Dd];
__device__ __align__(16) __nv_bfloat16 g_p_l[(size_t)Kp * Dd];
__device__ __align__(16) __nv_bfloat16 g_r_h[(size_t)Bq * Kp];
__device__ __align__(16) __nv_bfloat16 g_r_l[(size_t)Bq * Kp];
__device__ __align__(16) float g_logits[(size_t)Bq * Kp];
__device__ __align__(16) float g_parts[(size_t)NSLAB * Kp * Dd];

// ============================ PTX helpers (base sm_103-safe) =================
__device__ __forceinline__ uint32_t smem_u32(const void* p) {
    uint32_t a;
    asm("{ .reg .u64 t; cvta.to.shared.u64 t, %1; cvt.u32.u64 %0, t; }" : "=r"(a) : "l"(p));
    return a;
}
#define CP_ASYNC16(sa, gp) \
    asm volatile("cp.async.cg.shared.global [%0], [%1], 16;" :: "r"(sa), "l"(gp))
#define CP_COMMIT() asm volatile("cp.async.commit_group;")
#define CP_WAIT1()  asm volatile("cp.async.wait_group 1;")
#define LDSM_X4(r0, r1, r2, r3, addr) \
    asm volatile("ldmatrix.sync.aligned.m8n8.x4.shared.b16 {%0,%1,%2,%3}, [%4];" \
        : "=r"(r0), "=r"(r1), "=r"(r2), "=r"(r3) : "r"(addr))
#define LDSM_X4T(r0, r1, r2, r3, addr) \
    asm volatile("ldmatrix.sync.aligned.m8n8.x4.trans.shared.b16 {%0,%1,%2,%3}, [%4];" \
        : "=r"(r0), "=r"(r1), "=r"(r2), "=r"(r3) : "r"(addr))
#define MMA16816(d, a, b0v, b1v) \
    asm volatile("mma.sync.aligned.m16n8k16.row.col.f32.bf16.bf16.f32 " \
        "{%0,%1,%2,%3}, {%4,%5,%6,%7}, {%8,%9}, {%0,%1,%2,%3};" \
        : "+f"((d)[0]), "+f"((d)[1]), "+f"((d)[2]), "+f"((d)[3]) \
        : "r"((a)[0]), "r"((a)[1]), "r"((a)[2]), "r"((a)[3]), "r"(b0v), "r"(b1v))

// Tiles: CTA 128x128, 8 warps (2x4), warp 64x32, 4x4 of m16n8, KC=32, 3 stages.
#define KC 32
#define SROW 40
#define TROW 136
#define NT_STG (128 * SROW * 2)        // 10240 B
#define TT_STG (KC * TROW * 2)         // 8704 B
#define SMEM_NT (6 * NT_STG)           // 61440
#define SMEM_TT (6 * TT_STG)           // 52224
#define SMEM_NN (3 * NT_STG + 3 * TT_STG)  // 56832

// ---------------- shared epilogue ----------------
__device__ __forceinline__ void epilogue(float acc[4][4][4], float* C, int ldc,
                                         int bm, int bn, int wm, int wn, int lane,
                                         const float* addsrc)
{
#pragma unroll
    for (int mt = 0; mt < 4; ++mt) {
        const int r0 = bm + wm * 64 + mt * 16 + (lane >> 2);
#pragma unroll
        for (int nt = 0; nt < 4; ++nt) {
            const int col = bn + wn * 32 + nt * 8 + (lane & 3) * 2;
            float2 v0 = make_float2(acc[mt][nt][0], acc[mt][nt][1]);
            float2 v1 = make_float2(acc[mt][nt][2], acc[mt][nt][3]);
            if (addsrc) {
                const float2 a0 = *(const float2*)(addsrc + (size_t)r0 * ldc + col);
                const float2 a1 = *(const float2*)(addsrc + (size_t)(r0 + 8) * ldc + col);
                v0.x += a0.x; v0.y += a0.y;
                v1.x += a1.x; v1.y += a1.y;
            }
            *(float2*)(C + (size_t)r0 * ldc + col) = v0;
            *(float2*)(C + (size_t)(r0 + 8) * ldc + col) = v1;
        }
    }
}

// ============================ GEMM NT: logits = cls @ p^T (3-term) ===========
__global__ void __launch_bounds__(256, 2)
gemm_nt(const __nv_bfloat16* __restrict__ Ah, const __nv_bfloat16* __restrict__ Al, int lda,
        const __nv_bfloat16* __restrict__ Bh, const __nv_bfloat16* __restrict__ Bl, int ldb,
        int Ksrc, float* __restrict__ C, int ldc)
{
    extern __shared__ char smem[];
    const uint32_t sAb = smem_u32(smem);
    const uint32_t sBb = sAb + 3 * NT_STG;
    const int tid = threadIdx.x, lane = tid & 31, wid = tid >> 5;
    const int wm = wid >> 2, wn = wid & 3;
    const int bm = blockIdx.y * 128, bn = blockIdx.x * 128;

    float acc[4][4][4] = {};
    const int cpb = Ksrc / KC, nch = 3 * cpb;
    const int lrow = tid >> 2, lcb = (tid & 3) * 16;

    auto issue = [&](int c) {
        const int stg = c % 3;
        const int t = c / cpb;
        const size_t kk = (size_t)(c - t * cpb) * KC;
        const __nv_bfloat16* As = (t == 1) ? Al : Ah;
        const __nv_bfloat16* Bs = (t == 2) ? Bl : Bh;
        const uint32_t sa = sAb + stg * NT_STG, sb = sBb + stg * NT_STG;
#pragma unroll
        for (int it = 0; it < 2; ++it) {
            int row = lrow + it * 64;
            CP_ASYNC16(sa + row * 80 + lcb, As + (size_t)(bm + row) * lda + kk + lcb / 2);
            CP_ASYNC16(sb + row * 80 + lcb, Bs + (size_t)(bn + row) * ldb + kk + lcb / 2);
        }
        CP_COMMIT();
    };

    issue(0); issue(1);
    for (int c = 0; c < nch; ++c) {
        CP_WAIT1();
        __syncthreads();
        const int buf = c % 3;
        const uint32_t sa = sAb + buf * NT_STG, sb = sBb + buf * NT_STG;
#pragma unroll
        for (int kg = 0; kg < 2; ++kg) {
            const int kb = kg * 32;
            uint32_t a[4][4], bf[2][4];
#pragma unroll
            for (int mt = 0; mt < 4; ++mt) {
                uint32_t ad = sa + (uint32_t)(wm * 64 + mt * 16 + (lane & 15)) * 80
                            + kb + ((lane >> 4) << 4);
                LDSM_X4(a[mt][0], a[mt][1], a[mt][2], a[mt][3], ad);
            }
#pragma unroll
            for (int nh = 0; nh < 2; ++nh) {
                uint32_t bd = sb + (uint32_t)(wn * 32 + nh * 16 + ((lane >> 3) & 1) * 8 + (lane & 7)) * 80
                            + kb + ((lane >> 4) << 4);
                LDSM_X4(bf[nh][0], bf[nh][1], bf[nh][2], bf[nh][3], bd);
            }
#pragma unroll
            for (int nt = 0; nt < 4; ++nt) {
                const int nh = nt >> 1, lo = nt & 1;
                const uint32_t b0 = bf[nh][lo], b1 = bf[nh][lo + 2];
#pragma unroll
                for (int mt = 0; mt < 4; ++mt)
                    MMA16816(acc[mt][nt], a[mt], b0, b1);
            }
        }
        if (c + 2 < nch) issue(c + 2);
    }
    epilogue(acc, C, ldc, bm, bn, wm, wn, lane, nullptr);
}

// ============================ GEMM TT: parts[slab] = r^T @ cls (3-term) ======
// 9 uneven K-slabs: slab z covers chunks [z*28 + min(z,4), +28+(z<4)) of Bq/KC.
__global__ void __launch_bounds__(256, 2)
gemm_tt(const __nv_bfloat16* __restrict__ Ah, const __nv_bfloat16* __restrict__ Al, int lda,
        const __nv_bfloat16* __restrict__ Bh, const __nv_bfloat16* __restrict__ Bl, int ldb,
        float* __restrict__ C, int ldc, size_t zstride)
{
    extern __shared__ char smem[];
    const uint32_t sRb = smem_u32(smem);
    const uint32_t sCb = sRb + 3 * TT_STG;
    const int tid = threadIdx.x, lane = tid & 31, wid = tid >> 5;
    const int wm = wid >> 2, wn = wid & 3;
    const int bm = blockIdx.y * 128, bn = blockIdx.x * 128;
    const int z = blockIdx.z;
    const int cpb = 28 + (z < 4);                      // chunks in this slab
    const int b0seg = (z * 28 + min(z, 4)) * KC;       // starting row
    C += (size_t)z * zstride;

    float acc[4][4][4] = {};
    const int nch = 3 * cpb;
    const int lrow = tid >> 3, lc16 = (tid & 7) * 16;

    auto issue = [&](int c) {
        const int stg = c % 3;
        const int t = c / cpb;
        const int kk = (c - t * cpb) * KC;
        const __nv_bfloat16* As = (t == 1) ? Al : Ah;
        const __nv_bfloat16* Bs = (t == 2) ? Bl : Bh;
        const uint32_t sr = sRb + stg * TT_STG, sc = sCb + stg * TT_STG;
        const size_t gb = (size_t)(b0seg + kk + lrow);
        CP_ASYNC16(sr + lrow * 272 + lc16 * 2,      As + gb * lda + bm + lc16);
        CP_ASYNC16(sr + lrow * 272 + lc16 * 2 + 16, As + gb * lda + bm + lc16 + 8);
        CP_ASYNC16(sc + lrow * 272 + lc16 * 2,      Bs + gb * ldb + bn + lc16);
        CP_ASYNC16(sc + lrow * 272 + lc16 * 2 + 16, Bs + gb * ldb + bn + lc16 + 8);
        CP_COMMIT();
    };

    issue(0); issue(1);
    for (int c = 0; c < nch; ++c) {
        CP_WAIT1();
        __syncthreads();
        const int buf = c % 3;
        const uint32_t sr = sRb + buf * TT_STG, sc = sCb + buf * TT_STG;
#pragma unroll
        for (int kg = 0; kg < 2; ++kg) {
            uint32_t a[4][4], bf[2][4];
#pragma unroll
            for (int mt = 0; mt < 4; ++mt) {
                uint32_t ad = sr + (uint32_t)(kg * 16 + ((lane >> 4) << 3) + (lane & 7)) * 272
                            + (uint32_t)(wm * 64 + mt * 16 + ((lane >> 3) & 1) * 8) * 2;
                LDSM_X4T(a[mt][0], a[mt][1], a[mt][2], a[mt][3], ad);
            }
#pragma unroll
            for (int nh = 0; nh < 2; ++nh) {
                uint32_t bd = sc + (uint32_t)(kg * 16 + ((lane >> 3) & 1) * 8 + (lane & 7)) * 272
                            + (uint32_t)(wn * 32 + nh * 16 + ((lane >> 4) << 3)) * 2;
                LDSM_X4T(bf[nh][0], bf[nh][1], bf[nh][2], bf[nh][3], bd);
            }
#pragma unroll
            for (int nt = 0; nt < 4; ++nt) {
                const int nh = nt >> 1, w = nt & 1;
                const uint32_t b0 = bf[nh][w * 2], b1 = bf[nh][w * 2 + 1];
#pragma unroll
                for (int mt = 0; mt < 4; ++mt)
                    MMA16816(acc[mt][nt], a[mt], b0, b1);
            }
        }
        if (c + 2 < nch) issue(c + 2);
    }
    epilogue(acc, C, ldc, bm, bn, wm, wn, lane, nullptr);
}

// ============================ GEMM NN (1-term): z = r_h @ p_h + cls ==========
__global__ void __launch_bounds__(256, 2)
gemm_nn(const __nv_bfloat16* __restrict__ Ah, int lda,
        const __nv_bfloat16* __restrict__ Bh, int ldb,
        int Ksrc, float* __restrict__ C, int ldc, const float* __restrict__ addsrc)
{
    extern __shared__ char smem[];
    const uint32_t sAb = smem_u32(smem);
    const uint32_t sBb = sAb + 3 * NT_STG;
    const int tid = threadIdx.x, lane = tid & 31, wid = tid >> 5;
    const int wm = wid >> 2, wn = wid & 3;
    const int bm = blockIdx.y * 128, bn = blockIdx.x * 128;

    float acc[4][4][4] = {};
    const int nch = Ksrc / KC;
    const int lrow = tid >> 2, lcb = (tid & 3) * 16;
    const int trow = tid >> 3, tc16 = (tid & 7) * 16;

    auto issue = [&](int c) {
        const int stg = c % 3;
        const int kk = c * KC;
        const uint32_t sa = sAb + stg * NT_STG, sb = sBb + stg * TT_STG;
#pragma unroll
        for (int it = 0; it < 2; ++it) {
            int row = lrow + it * 64;
            CP_ASYNC16(sa + row * 80 + lcb, Ah + (size_t)(bm + row) * lda + kk + lcb / 2);
        }
        CP_ASYNC16(sb + trow * 272 + tc16 * 2,      Bh + (size_t)(kk + trow) * ldb + bn + tc16);
        CP_ASYNC16(sb + trow * 272 + tc16 * 2 + 16, Bh + (size_t)(kk + trow) * ldb + bn + tc16 + 8);
        CP_COMMIT();
    };

    issue(0); issue(1);
    for (int c = 0; c < nch; ++c) {
        CP_WAIT1();
        __syncthreads();
        const int buf = c % 3;
        const uint32_t sa = sAb + buf * NT_STG, sb = sBb + buf * TT_STG;
#pragma unroll
        for (int kg = 0; kg < 2; ++kg) {
            const int kb = kg * 32;
            uint32_t a[4][4], bf[2][4];
#pragma unroll
            for (int mt = 0; mt < 4; ++mt) {
                uint32_t ad = sa + (uint32_t)(wm * 64 + mt * 16 + (lane & 15)) * 80
                            + kb + ((lane >> 4) << 4);
                LDSM_X4(a[mt][0], a[mt][1], a[mt][2], a[mt][3], ad);
            }
#pragma unroll
            for (int nh = 0; nh < 2; ++nh) {
                uint32_t bd = sb + (uint32_t)(kg * 16 + ((lane >> 3) & 1) * 8 + (lane & 7)) * 272
                            + (uint32_t)(wn * 32 + nh * 16 + ((lane >> 4) << 3)) * 2;
                LDSM_X4T(bf[nh][0], bf[nh][1], bf[nh][2], bf[nh][3], bd);
            }
#pragma unroll
            for (int nt = 0; nt < 4; ++nt) {
                const int nh = nt >> 1, w = nt & 1;
                const uint32_t b0 = bf[nh][w * 2], b1 = bf[nh][w * 2 + 1];
#pragma unroll
                for (int mt = 0; mt < 4; ++mt)
                    MMA16816(acc[mt][nt], a[mt], b0, b1);
            }
        }
        if (c + 2 < nch) issue(c + 2);
    }
    epilogue(acc, C, ldc, bm, bn, wm, wn, lane, addsrc);
}

// ============================ split fp32 -> bf16 hi/lo (fused both inputs) ===
__global__ void __launch_bounds__(256)
split_both(const float* __restrict__ x1, __nv_bfloat16* __restrict__ h1,
           __nv_bfloat16* __restrict__ l1, int n1,
           const float* __restrict__ x2, __nv_bfloat16* __restrict__ h2,
           __nv_bfloat16* __restrict__ l2, int n2)
{
    const int nb1 = n1 / 1024;
    const float* x; __nv_bfloat16 *h, *l;
    int i;
    if ((int)blockIdx.x < nb1) {
        x = x1; h = h1; l = l1;
        i = (blockIdx.x * 256 + threadIdx.x) * 4;
        if (i >= n1) return;
    } else {
        x = x2; h = h2; l = l2;
        i = ((blockIdx.x - nb1) * 256 + threadIdx.x) * 4;
        if (i >= n2) return;
    }
    float4 v = *(const float4*)(x + i);
    __nv_bfloat16 h0 = __float2bfloat16(v.x), h1v = __float2bfloat16(v.y);
    __nv_bfloat16 h2v = __float2bfloat16(v.z), h3 = __float2bfloat16(v.w);
    __nv_bfloat16 l0 = __float2bfloat16(v.x - __bfloat162float(h0));
    __nv_bfloat16 l1v = __float2bfloat16(v.y - __bfloat162float(h1v));
    __nv_bfloat16 l2v = __float2bfloat16(v.z - __bfloat162float(h2v));
    __nv_bfloat16 l3 = __float2bfloat16(v.w - __bfloat162float(h3));
    ((__nv_bfloat162*)(h + i))[0] = __halves2bfloat162(h0, h1v);
    ((__nv_bfloat162*)(h + i))[1] = __halves2bfloat162(h2v, h3);
    ((__nv_bfloat162*)(l + i))[0] = __halves2bfloat162(l0, l1v);
    ((__nv_bfloat162*)(l + i))[1] = __halves2bfloat162(l2v, l3);
}

// ============================ softmax: one warp per 512-col row ==============
__global__ void __launch_bounds__(256)
softmax_warp(const float* __restrict__ L, __nv_bfloat16* __restrict__ rh,
             __nv_bfloat16* __restrict__ rl, float* __restrict__ rf)
{
    const int row = blockIdx.x * 8 + (threadIdx.x >> 5);
    const int lane = threadIdx.x & 31;
    const float4* Lr = (const float4*)(L + (size_t)row * Kp);

    float4 v[4];
#pragma unroll
    for (int j = 0; j < 4; ++j) v[j] = Lr[lane + j * 32];

    float m = -1e30f;
#pragma unroll
    for (int j = 0; j < 4; ++j)
        m = fmaxf(m, fmaxf(fmaxf(v[j].x, v[j].y), fmaxf(v[j].z, v[j].w)));
#pragma unroll
    for (int o = 16; o; o >>= 1) m = fmaxf(m, __shfl_xor_sync(0xffffffffu, m, o));

    float4 e[4];
    float s = 0.f;
#pragma unroll
    for (int j = 0; j < 4; ++j) {
        e[j].x = __expf(v[j].x - m); e[j].y = __expf(v[j].y - m);
        e[j].z = __expf(v[j].z - m); e[j].w = __expf(v[j].w - m);
        s += (e[j].x + e[j].y) + (e[j].z + e[j].w);
    }
#pragma unroll
    for (int o = 16; o; o >>= 1) s += __shfl_xor_sync(0xffffffffu, s, o);

    const float inv = 1.0f / s;
    __nv_bfloat162* hp = (__nv_bfloat162*)(rh + (size_t)row * Kp);
    __nv_bfloat162* lp = (__nv_bfloat162*)(rl + (size_t)row * Kp);
    float4* rp = rf ? (float4*)(rf + (size_t)row * Kp) : nullptr;
#pragma unroll
    for (int j = 0; j < 4; ++j) {
        e[j].x *= inv; e[j].y *= inv; e[j].z *= inv; e[j].w *= inv;
        __nv_bfloat16 h0 = __float2bfloat16(e[j].x), h1 = __float2bfloat16(e[j].y);
        __nv_bfloat16 h2 = __float2bfloat16(e[j].z), h3 = __float2bfloat16(e[j].w);
        const int c2 = (lane + j * 32) * 2;
        hp[c2 + 0] = __halves2bfloat162(h0, h1);
        hp[c2 + 1] = __halves2bfloat162(h2, h3);
        if (rp) {
            rp[lane + j * 32] = e[j];
        } else {
            __nv_bfloat16 l0 = __float2bfloat16(e[j].x - __bfloat162float(h0));
            __nv_bfloat16 l1 = __float2bfloat16(e[j].y - __bfloat162float(h1));
            __nv_bfloat16 l2 = __float2bfloat16(e[j].z - __bfloat162float(h2));
            __nv_bfloat16 l3 = __float2bfloat16(e[j].w - __bfloat162float(h3));
            lp[c2 + 0] = __halves2bfloat162(l0, l1);
            lp[c2 + 1] = __halves2bfloat162(l2, l3);
        }
    }
}

// ============================ reduce NSLAB partials + L2 normalize ===========
__global__ void __launch_bounds__(256)
reduce_norm(const float* __restrict__ parts, __nv_bfloat16* __restrict__ ph,
            __nv_bfloat16* __restrict__ pl)
{
    const int k = blockIdx.x;
    const int tid = threadIdx.x;
    __shared__ float4 buf[Dd / 4];
    __shared__ float wred[8];
    __shared__ float sden;

    float4 s = make_float4(0.f, 0.f, 0.f, 0.f);
#pragma unroll
    for (int g = 0; g < NSLAB; ++g) {
        const float4 v = *(const float4*)(parts + (size_t)g * Kp * Dd + (size_t)k * Dd + tid * 4);
        s.x += v.x; s.y += v.y; s.z += v.z; s.w += v.w;
    }
    buf[tid] = s;
    float sq = s.x * s.x + s.y * s.y + s.z * s.z + s.w * s.w;
#pragma unroll
    for (int o = 16; o; o >>= 1) sq += __shfl_xor_sync(0xffffffffu, sq, o);
    if ((tid & 31) == 0) wred[tid >> 5] = sq;
    __syncthreads();
    if (tid == 0) {
        float t = 0.f;
#pragma unroll
        for (int i = 0; i < 8; ++i) t += wred[i];
        sden = sqrtf(t) + 1e-6f;
    }
    __syncthreads();
    const float inv = 1.0f / sden;
    const float4 b = buf[tid];
    float x0 = b.x * inv, x1 = b.y * inv, x2 = b.z * inv, x3 = b.w * inv;
    __nv_bfloat16 h0 = __float2bfloat16(x0), h1 = __float2bfloat16(x1);
    __nv_bfloat16 h2 = __float2bfloat16(x2), h3 = __float2bfloat16(x3);
    __nv_bfloat16 l0 = __float2bfloat16(x0 - __bfloat162float(h0));
    __nv_bfloat16 l1 = __float2bfloat16(x1 - __bfloat162float(h1));
    __nv_bfloat16 l2 = __float2bfloat16(x2 - __bfloat162float(h2));
    __nv_bfloat16 l3 = __float2bfloat16(x3 - __bfloat162float(h3));
    __nv_bfloat162* hp = (__nv_bfloat162*)(ph + (size_t)k * Dd + tid * 4);
    __nv_bfloat162* lp = (__nv_bfloat162*)(pl + (size_t)k * Dd + tid * 4);
    hp[0] = __halves2bfloat162(h0, h1);
    hp[1] = __halves2bfloat162(h2, h3);
    lp[0] = __halves2bfloat162(l0, l1);
    lp[1] = __halves2bfloat162(l2, l3);
}

// ============================ launcher =======================================
extern "C" void kernel_launch(void* const* d_in, const int* in_sizes, int n_in,
                              void* d_out, int out_size)
{
    const float* cls   = (const float*)d_in[0];
    const float* proto = (const float*)d_in[1];
    if (n_in >= 2 && in_sizes[0] < in_sizes[1]) {
        const float* t = cls; cls = proto; proto = t;
    }

    __nv_bfloat16 *cls_h, *cls_l, *p_h, *p_l, *r_h, *r_l;
    float *logits, *parts;
    cudaGetSymbolAddress((void**)&cls_h,  g_cls_h);
    cudaGetSymbolAddress((void**)&cls_l,  g_cls_l);
    cudaGetSymbolAddress((void**)&p_h,    g_p_h);
    cudaGetSymbolAddress((void**)&p_l,    g_p_l);
    cudaGetSymbolAddress((void**)&r_h,    g_r_h);
    cudaGetSymbolAddress((void**)&r_l,    g_r_l);
    cudaGetSymbolAddress((void**)&logits, g_logits);
    cudaGetSymbolAddress((void**)&parts,  g_parts);

    cudaFuncSetAttribute(gemm_nt, cudaFuncAttributeMaxDynamicSharedMemorySize, SMEM_NT);
    cudaFuncSetAttribute(gemm_tt, cudaFuncAttributeMaxDynamicSharedMemorySize, SMEM_TT);
    cudaFuncSetAttribute(gemm_nn, cudaFuncAttributeMaxDynamicSharedMemorySize, SMEM_NN);

    float* r_out = (float*)d_out;                          // [Bq, Kp]
    float* z_out = (float*)d_out + (size_t)Bq * Kp;        // [Bq, Dd]

    split_both<<<(Bq * Dd + Kp * Dd) / 1024, 256>>>(cls, cls_h, cls_l, Bq * Dd,
                                                    proto, p_h, p_l, Kp * Dd);

    dim3 g1(Kp / 128, Bq / 128);            // (4, 64)
    dim3 g2(Dd / 128, Kp / 128, NSLAB);     // (8, 4, 9) = 288 CTAs, 1 wave
    dim3 g3(Dd / 128, Bq / 128);            // (8, 64)

    for (int s = 0; s < STAGES; ++s) {
        gemm_nt<<<g1, 256, SMEM_NT>>>(cls_h, cls_l, Dd, p_h, p_l, Dd,
                                      Dd, logits, Kp);
        softmax_warp<<<Bq / 8, 256>>>(logits, r_h, r_l, nullptr);
        gemm_tt<<<g2, 256, SMEM_TT>>>(r_h, r_l, Kp, cls_h, cls_l, Dd,
                                      parts, Dd, (size_t)Kp * Dd);
        reduce_norm<<<Kp, 256>>>(parts, p_h, p_l);
    }

    gemm_nt<<<g1, 256, SMEM_NT>>>(cls_h, cls_l, Dd, p_h, p_l, Dd,
                                  Dd, logits, Kp);
    softmax_warp<<<Bq / 8, 256>>>(logits, r_h, r_l, r_out);
    gemm_nn<<<g3, 256, SMEM_NN>>>(r_h, Kp, p_h, Dd,
                                  Kp, z_out, Dd, cls);
}